// round 4
// baseline (speedup 1.0000x reference)
#include <cuda_runtime.h>
#include <math.h>

#define NB    1024
#define NCP   20000
#define NF    10001
#define NPAIR 512
// 20000 = 125 * 160;  n = n1 + 125*n2, k = 160*k1 + k2
// Stage1: T[n1][k2] = (sum_n2 z[n1+125*n2] * W160^{n2*k2}) * W20000^{n1*k2}
// Stage2: Z[160*k1+k2] = sum_n1 T[n1][k2] * W125^{n1*k1}

// ---------------- device scratch (no allocations allowed) ----------------
__device__ float2 g_bufA[NPAIR * NCP];
__device__ float2 g_bufB[NPAIR * NCP];
__device__ float  g_h[NB * NF];
__device__ float  g_S0[256 * NF];
__device__ float  g_S1[128 * 256];
__device__ float  g_S2[64 * 128];
__device__ float  g_mean[NB];
__device__ float  g_invn0[NB];
__device__ float  g_invn1[NB];
__device__ float  g_invn2[NB];
__device__ float  g_invn3[NB];
__device__ float  g_Y[NB * 256];
__device__ float  g_P[NB * 256];
__device__ float  g_act1[NB * 256];
__device__ float  g_act2[NB * 128];
__device__ float  g_act3[NB * 64];
__device__ float2 g_w160[160];
__device__ float2 g_w125[125];
__device__ float2 g_w20000[NCP];

// ---------------- helpers ----------------
__device__ __forceinline__ void cfma(float2& a, float2 z, float2 w) {
    a.x = fmaf(z.x, w.x, a.x); a.x = fmaf(-z.y, w.y, a.x);
    a.y = fmaf(z.x, w.y, a.y); a.y = fmaf(z.y, w.x, a.y);
}
__device__ __forceinline__ float2 cmul(float2 a, float2 w) {
    return make_float2(a.x * w.x - a.y * w.y, a.x * w.y + a.y * w.x);
}
__device__ __forceinline__ float blockReduce(float v, float* sb, int tid, int n) {
    sb[tid] = v; __syncthreads();
    for (int s = n >> 1; s > 0; s >>= 1) {
        if (tid < s) sb[tid] += sb[tid + s];
        __syncthreads();
    }
    float r = sb[0]; __syncthreads();
    return r;
}

// ---------------- init kernels (per launch; deterministic) ----------------
__global__ void twiddle_init_k() {
    int i = blockIdx.x * blockDim.x + threadIdx.x;
    if (i < NCP) {
        double s, c; sincospi(-2.0 * (double)i / 20000.0, &s, &c);
        g_w20000[i] = make_float2((float)c, (float)s);
    }
    if (i < 160) {
        double s, c; sincospi(-2.0 * (double)i / 160.0, &s, &c);
        g_w160[i] = make_float2((float)c, (float)s);
    }
    if (i < 125) {
        double s, c; sincospi(-2.0 * (double)i / 125.0, &s, &c);
        g_w125[i] = make_float2((float)c, (float)s);
    }
}

__global__ void sigmoid_k(const float* __restrict__ a, float* __restrict__ s, int n) {
    for (int i = blockIdx.x * blockDim.x + threadIdx.x; i < n; i += gridDim.x * blockDim.x)
        s[i] = 1.0f / (1.0f + expf(-a[i]));
}

// ---------------- row means ----------------
__global__ void mean_k(const float* __restrict__ x) {
    __shared__ float sb[256];
    int r = blockIdx.x;
    const float* xr = x + (size_t)r * NCP;
    float s = 0.f;
    for (int i = threadIdx.x; i < NCP; i += 256) s += xr[i];
    float tot = blockReduce(s, sb, threadIdx.x, 256);
    if (threadIdx.x == 0) g_mean[r] = tot * (1.0f / 20000.0f);
}

// ---------------- FFT stage 1: 160-pt DFTs + twiddle ----------------
__global__ void __launch_bounds__(1024, 1) stage1_k(const float* __restrict__ x) {
    extern __shared__ float2 sm1[];
    float2* z  = sm1;           // 20001 entries (1 pad)
    float2* tw = sm1 + 20001;   // 160 entries
    int p = blockIdx.x, t = threadIdx.x;
    const float* xa = x + (size_t)(2 * p) * NCP;
    const float* xb = xa + NCP;
    float ma = g_mean[2 * p], mb = g_mean[2 * p + 1];
    for (int i = t; i < NCP; i += 1024) z[i] = make_float2(xa[i] - ma, xb[i] - mb);
    if (t == 0) z[NCP] = make_float2(0.f, 0.f);
    if (t < 160) tw[t] = g_w160[t];
    __syncthreads();

    float2* out = g_bufA + (size_t)p * NCP;
    for (int g = t; g < 63 * 80; g += 1024) {
        int n1p = g / 80, k2i = g % 80;
        int n1 = 2 * n1p;
        int k2a = k2i, k2b = k2i + 80;
        float2 a00 = make_float2(0.f, 0.f), a01 = a00, a10 = a00, a11 = a00;
        int ia = 0, ib = 0, base = n1;
        #pragma unroll 5
        for (int n2 = 0; n2 < 160; n2++) {
            float2 za = z[base], zb = z[base + 1];
            float2 wA = tw[ia], wB = tw[ib];
            cfma(a00, za, wA); cfma(a01, za, wB);
            cfma(a10, zb, wA); cfma(a11, zb, wB);
            ia += k2a; if (ia >= 160) ia -= 160;
            ib += k2b; if (ib >= 160) ib -= 160;
            base += 125;
        }
        out[n1 * 160 + k2a] = cmul(a00, g_w20000[n1 * k2a]);
        out[n1 * 160 + k2b] = cmul(a01, g_w20000[n1 * k2b]);
        if (n1 + 1 < 125) {
            out[(n1 + 1) * 160 + k2a] = cmul(a10, g_w20000[(n1 + 1) * k2a]);
            out[(n1 + 1) * 160 + k2b] = cmul(a11, g_w20000[(n1 + 1) * k2b]);
        }
    }
}

// ---------------- FFT stage 2: 125-pt DFTs ----------------
__global__ void __launch_bounds__(1024, 1) stage2_k() {
    extern __shared__ float2 sm2[];
    float2* T  = sm2;          // 20000
    float2* tw = sm2 + 20000;  // 125
    int p = blockIdx.x, t = threadIdx.x;
    const float2* in = g_bufA + (size_t)p * NCP;
    for (int i = t; i < NCP; i += 1024) T[i] = in[i];
    if (t < 125) tw[t] = g_w125[t];
    __syncthreads();

    float2* out = g_bufB + (size_t)p * NCP;
    for (int g = t; g < 63 * 80; g += 1024) {
        int k1p = g / 80, k2i = g % 80;
        int k1 = 2 * k1p;
        float2 a00 = make_float2(0.f, 0.f), a01 = a00, a10 = a00, a11 = a00;
        int ia = 0, ib = 0;
        const float2* Tr = T;
        #pragma unroll 5
        for (int n1 = 0; n1 < 125; n1++) {
            float2 ta = Tr[k2i], tb = Tr[k2i + 80];
            float2 wA = tw[ia], wB = tw[ib];
            cfma(a00, ta, wA); cfma(a01, tb, wA);
            cfma(a10, ta, wB); cfma(a11, tb, wB);
            ia += k1;     if (ia >= 125) ia -= 125;
            ib += k1 + 1; if (ib >= 125) ib -= 125;
            Tr += 160;
        }
        out[160 * k1 + k2i]      = a00;
        out[160 * k1 + k2i + 80] = a01;
        if (k1 + 1 < 125) {
            out[160 * (k1 + 1) + k2i]      = a10;
            out[160 * (k1 + 1) + k2i + 80] = a11;
        }
    }
}

// ------------- unpack packed pair + log1p|.| + row norms -------------
__global__ void unpack_k() {
    __shared__ float sb[256];
    int p = blockIdx.x, t = threadIdx.x;
    const float2* Z = g_bufB + (size_t)p * NCP;
    float* ha = g_h + (size_t)(2 * p) * NF;
    float* hb = ha + NF;
    float sa = 0.f, sbv = 0.f;
    for (int k = t; k < NF; k += 256) {
        float2 zk = Z[k];
        float2 zr = Z[(NCP - k) % NCP];
        float are = 0.5f * (zk.x + zr.x), aim = 0.5f * (zk.y - zr.y);
        float bre = 0.5f * (zk.y + zr.y), bim = 0.5f * (zr.x - zk.x);
        float va = log1pf(sqrtf(fmaf(are, are, aim * aim)));
        float vb = log1pf(sqrtf(fmaf(bre, bre, bim * bim)));
        ha[k] = va; hb[k] = vb;
        sa  = fmaf(va, va, sa);
        sbv = fmaf(vb, vb, sbv);
    }
    float s1 = blockReduce(sa, sb, t, 256);
    float s2 = blockReduce(sbv, sb, t, 256);
    if (t == 0) {
        g_invn0[2 * p]     = 1.0f / (sqrtf(s1) + 1e-8f);
        g_invn0[2 * p + 1] = 1.0f / (sqrtf(s2) + 1e-8f);
    }
}

// ------------- dual GEMM: Y = A W^T,  P = (A∘A) S^T -------------
__global__ void __launch_bounds__(256) gemm_dual_k(
    const float* __restrict__ A, const float* __restrict__ W, const float* __restrict__ S,
    float* __restrict__ Y, float* __restrict__ P, int M, int N, int K)
{
    __shared__ float sA[32][33], sW[32][33], sS[32][33];
    int t = threadIdx.x, tx = t & 15, ty = t >> 4;
    int m0 = blockIdx.y * 32, n0 = blockIdx.x * 32;
    float y00 = 0.f, y01 = 0.f, y10 = 0.f, y11 = 0.f;
    float p00 = 0.f, p01 = 0.f, p10 = 0.f, p11 = 0.f;

    for (int k0 = 0; k0 < K; k0 += 32) {
        #pragma unroll
        for (int i = 0; i < 4; i++) {
            int e = t + i * 256;
            int kk = e & 31, mm = e >> 5;
            int gk = k0 + kk;
            bool ok = gk < K;
            sA[kk][mm] = ok ? A[(size_t)(m0 + mm) * K + gk] : 0.f;
            sW[kk][mm] = ok ? W[(size_t)(n0 + mm) * K + gk] : 0.f;
            sS[kk][mm] = ok ? S[(size_t)(n0 + mm) * K + gk] : 0.f;
        }
        __syncthreads();
        #pragma unroll
        for (int kk = 0; kk < 32; kk++) {
            float a0 = sA[kk][2 * ty], a1 = sA[kk][2 * ty + 1];
            float a0s = a0 * a0, a1s = a1 * a1;
            float w0 = sW[kk][2 * tx], w1 = sW[kk][2 * tx + 1];
            float s0 = sS[kk][2 * tx], s1v = sS[kk][2 * tx + 1];
            y00 = fmaf(a0, w0, y00);  y01 = fmaf(a0, w1, y01);
            y10 = fmaf(a1, w0, y10);  y11 = fmaf(a1, w1, y11);
            p00 = fmaf(a0s, s0, p00); p01 = fmaf(a0s, s1v, p01);
            p10 = fmaf(a1s, s0, p10); p11 = fmaf(a1s, s1v, p11);
        }
        __syncthreads();
    }
    int m = m0 + 2 * ty, n = n0 + 2 * tx;
    Y[(size_t)m * N + n] = y00;           Y[(size_t)m * N + n + 1] = y01;
    Y[(size_t)(m + 1) * N + n] = y10;     Y[(size_t)(m + 1) * N + n + 1] = y11;
    P[(size_t)m * N + n] = p00;           P[(size_t)m * N + n + 1] = p01;
    P[(size_t)(m + 1) * N + n] = p10;     P[(size_t)(m + 1) * N + n + 1] = p11;
}

// ------------- epilogue: plastic + LayerNorm + exact GELU + next norm -------------
__global__ void epi_k(const float* __restrict__ Y, const float* __restrict__ P,
                      const float* __restrict__ b, const float* __restrict__ eta,
                      const float* __restrict__ g, const float* __restrict__ be,
                      const float* __restrict__ invn_in,
                      float* __restrict__ act, float* __restrict__ invn_out, int H)
{
    __shared__ float sb[256];
    int r = blockIdx.x, o = threadIdx.x;
    float ys = Y[(size_t)r * H + o] + b[o];
    float y = fmaf(eta[0] * tanhf(ys), invn_in[r] * P[(size_t)r * H + o], ys);
    float invH = 1.0f / (float)H;
    float s1 = blockReduce(y, sb, o, H);
    float s2 = blockReduce(y * y, sb, o, H);
    float mu = s1 * invH;
    float var = fmaf(s2, invH, -mu * mu);
    float ln = (y - mu) * rsqrtf(var + 1e-5f) * g[o] + be[o];
    float a = 0.5f * ln * (1.0f + erff(ln * 0.70710678118654752f));
    act[(size_t)r * H + o] = a;
    float s3 = blockReduce(a * a, sb, o, H);
    if (o == 0) invn_out[r] = 1.0f / (sqrtf(s3) + 1e-8f);
}

// ------------- head -------------
__global__ void head_k(const float* __restrict__ act, const float* __restrict__ hw,
                       const float* __restrict__ hb, float* __restrict__ out)
{
    int t = threadIdx.x;
    int warp = t >> 5, lane = t & 31;
    int r = blockIdx.x * 32 + warp;
    const float* a = act + (size_t)r * 64;
    float v = fmaf(a[lane], hw[lane], a[lane + 32] * hw[lane + 32]);
    #pragma unroll
    for (int off = 16; off > 0; off >>= 1) v += __shfl_down_sync(0xffffffffu, v, off);
    if (lane == 0) out[r] = v + hb[0];
}

// ---------------- host launch ----------------
extern "C" void kernel_launch(void* const* d_in, const int* in_sizes, int n_in,
                              void* d_out, int out_size)
{
    (void)in_sizes; (void)n_in; (void)out_size;
    const float* x    = (const float*)d_in[0];
    const float* W0   = (const float*)d_in[1];
    const float* al0  = (const float*)d_in[2];
    const float* b0   = (const float*)d_in[3];
    const float* eta0 = (const float*)d_in[4];
    const float* g0   = (const float*)d_in[5];
    const float* be0  = (const float*)d_in[6];
    const float* W1   = (const float*)d_in[7];
    const float* al1  = (const float*)d_in[8];
    const float* b1   = (const float*)d_in[9];
    const float* eta1 = (const float*)d_in[10];
    const float* g1   = (const float*)d_in[11];
    const float* be1  = (const float*)d_in[12];
    const float* W2   = (const float*)d_in[13];
    const float* al2  = (const float*)d_in[14];
    const float* b2   = (const float*)d_in[15];
    const float* eta2 = (const float*)d_in[16];
    const float* g2   = (const float*)d_in[17];
    const float* be2  = (const float*)d_in[18];
    const float* hw   = (const float*)d_in[19];
    const float* hb   = (const float*)d_in[20];
    float* out = (float*)d_out;

    float *pS0, *pS1, *pS2, *ph, *pY, *pP, *pa1, *pa2, *pa3, *pi0, *pi1, *pi2, *pi3;
    cudaGetSymbolAddress((void**)&pS0, g_S0);
    cudaGetSymbolAddress((void**)&pS1, g_S1);
    cudaGetSymbolAddress((void**)&pS2, g_S2);
    cudaGetSymbolAddress((void**)&ph,  g_h);
    cudaGetSymbolAddress((void**)&pY,  g_Y);
    cudaGetSymbolAddress((void**)&pP,  g_P);
    cudaGetSymbolAddress((void**)&pa1, g_act1);
    cudaGetSymbolAddress((void**)&pa2, g_act2);
    cudaGetSymbolAddress((void**)&pa3, g_act3);
    cudaGetSymbolAddress((void**)&pi0, g_invn0);
    cudaGetSymbolAddress((void**)&pi1, g_invn1);
    cudaGetSymbolAddress((void**)&pi2, g_invn2);
    cudaGetSymbolAddress((void**)&pi3, g_invn3);

    const int SMEM1 = (20001 + 160) * (int)sizeof(float2); // 161288 B
    const int SMEM2 = (20000 + 125) * (int)sizeof(float2); // 161000 B
    cudaFuncSetAttribute(stage1_k, cudaFuncAttributeMaxDynamicSharedMemorySize, SMEM1);
    cudaFuncSetAttribute(stage2_k, cudaFuncAttributeMaxDynamicSharedMemorySize, SMEM2);

    twiddle_init_k<<<(NCP + 255) / 256, 256>>>();
    sigmoid_k<<<512, 256>>>(al0, pS0, 256 * NF);
    sigmoid_k<<<64, 256>>>(al1, pS1, 128 * 256);
    sigmoid_k<<<16, 256>>>(al2, pS2, 64 * 128);
    mean_k<<<NB, 256>>>(x);
    stage1_k<<<NPAIR, 1024, SMEM1>>>(x);
    stage2_k<<<NPAIR, 1024, SMEM2>>>();
    unpack_k<<<NPAIR, 256>>>();

    gemm_dual_k<<<dim3(256 / 32, NB / 32), 256>>>(ph,  W0, pS0, pY, pP, NB, 256, NF);
    epi_k<<<NB, 256>>>(pY, pP, b0, eta0, g0, be0, pi0, pa1, pi1, 256);
    gemm_dual_k<<<dim3(128 / 32, NB / 32), 256>>>(pa1, W1, pS1, pY, pP, NB, 128, 256);
    epi_k<<<NB, 128>>>(pY, pP, b1, eta1, g1, be1, pi1, pa2, pi2, 128);
    gemm_dual_k<<<dim3(64 / 32, NB / 32), 256>>>(pa2, W2, pS2, pY, pP, NB, 64, 128);
    epi_k<<<NB, 64>>>(pY, pP, b2, eta2, g2, be2, pi2, pa3, pi3, 64);
    head_k<<<NB / 32, 1024>>>(pa3, hw, hb, out);
}

// round 5
// speedup vs baseline: 2.6250x; 2.6250x over previous
#include <cuda_runtime.h>
#include <math.h>

#define NB     1024
#define NCP    20000
#define NF     10001
#define NPAIR  512
#define NSPLIT 4

// ---------------- device scratch (no allocations allowed) ----------------
__device__ float  g_h[NB * NF];
__device__ float  g_S0[256 * NF];
__device__ float  g_S1[128 * 256];
__device__ float  g_S2[64 * 128];
__device__ float  g_invn0[NB];
__device__ float  g_invn1[NB];
__device__ float  g_invn2[NB];
__device__ float  g_invn3[NB];
__device__ float  g_Yp[NSPLIT * NB * 256];
__device__ float  g_Pp[NSPLIT * NB * 256];
__device__ float  g_act1[NB * 256];
__device__ float  g_act2[NB * 128];
__device__ float  g_act3[NB * 64];
__device__ float2 g_w20000[2000];   // only indices < 2000 are ever used

// ---------------- helpers ----------------
__device__ __forceinline__ float2 cmul(float2 a, float2 b) {
    return make_float2(a.x * b.x - a.y * b.y, a.x * b.y + a.y * b.x);
}
__device__ __forceinline__ float blockReduce(float v, float* sb, int tid, int n) {
    sb[tid] = v; __syncthreads();
    for (int s = n >> 1; s > 0; s >>= 1) {
        if (tid < s) sb[tid] += sb[tid + s];
        __syncthreads();
    }
    float r = sb[0]; __syncthreads();
    return r;
}

// digit-reversed position after DIF radix sequence [10,10,10,10,2]
__device__ __forceinline__ int posidx(int k) {
    int d0 = k % 10; k /= 10;
    int d1 = k % 10; k /= 10;
    int d2 = k % 10; k /= 10;
    int d3 = k % 10; int d4 = k / 10;
    return d0 * 2000 + d1 * 200 + d2 * 20 + d3 * 2 + d4;
}

// ---------------- init kernels ----------------
__global__ void twiddle_init_k() {
    int i = blockIdx.x * blockDim.x + threadIdx.x;
    if (i < 2000) {
        double s, c; sincospi(-2.0 * (double)i / 20000.0, &s, &c);
        g_w20000[i] = make_float2((float)c, (float)s);
    }
}

__global__ void sigmoid_k(const float* __restrict__ a, float* __restrict__ s, int n) {
    for (int i = blockIdx.x * blockDim.x + threadIdx.x; i < n; i += gridDim.x * blockDim.x)
        s[i] = 1.0f / (1.0f + expf(-a[i]));
}

// ---------------- radix-10 in-place DIF stage (sub-size NN, stride MM=NN/10) ----
template<int NN, int MM>
__device__ __forceinline__ void r10_stage(float2* Z, const float2* tws, int t)
{
    constexpr float WR[10] = { 1.f,  0.8090169943749475f,  0.30901699437494745f,
                              -0.30901699437494745f, -0.8090169943749475f, -1.f,
                              -0.8090169943749475f, -0.30901699437494745f,
                               0.30901699437494745f,  0.8090169943749475f };
    constexpr float WI[10] = { 0.f, -0.5877852522924731f, -0.9510565162951535f,
                              -0.9510565162951535f, -0.5877852522924731f,  0.f,
                               0.5877852522924731f,  0.9510565162951535f,
                               0.9510565162951535f,  0.5877852522924731f };
    for (int g = t; g < 2000; g += 1024) {
        int blk = g / MM, j = g - blk * MM;
        int base = blk * NN + j;
        float2 c[10];
        #pragma unroll
        for (int u = 0; u < 10; u++) c[u] = Z[base + u * MM];
        float2 w1 = tws[(20000 / NN) * j];
        // v = 0: plain sum
        float sx = c[0].x, sy = c[0].y;
        #pragma unroll
        for (int u = 1; u < 10; u++) { sx += c[u].x; sy += c[u].y; }
        float2 tw = w1;
        #pragma unroll
        for (int v = 1; v < 10; v++) {
            float ax = c[0].x, ay = c[0].y;
            #pragma unroll
            for (int u = 1; u < 10; u++) {
                const int idx = (u * v) % 10;   // compile-time after unroll
                ax = fmaf(c[u].x, WR[idx], ax); ax = fmaf(-c[u].y, WI[idx], ax);
                ay = fmaf(c[u].x, WI[idx], ay); ay = fmaf( c[u].y, WR[idx], ay);
            }
            Z[base + v * MM] = make_float2(ax * tw.x - ay * tw.y,
                                           ax * tw.y + ay * tw.x);
            tw = cmul(tw, w1);
        }
        Z[base] = make_float2(sx, sy);
    }
}

// ---------- fused FFT (packed 2 rows) + unpack + log1p|.| + row norms ----------
// mean subtraction only changes bin 0 of the FFT (constant offset), so we FFT raw
// x and force h[...,0] = 0 (reference gets ~1e-5 there; weight 0.01 -> negligible).
__global__ void __launch_bounds__(1024, 1) fft_k(const float* __restrict__ x)
{
    extern __shared__ float2 sm[];
    float2* Z   = sm;           // 20000 complex, in-place FFT
    float2* tws = sm + 20000;   // 2000 twiddles
    __shared__ float sred[64];
    int p = blockIdx.x, t = threadIdx.x;
    const float* xa = x + (size_t)(2 * p) * NCP;
    const float* xb = xa + NCP;
    for (int i = t; i < NCP; i += 1024) Z[i] = make_float2(xa[i], xb[i]);
    for (int i = t; i < 2000; i += 1024) tws[i] = g_w20000[i];
    __syncthreads();

    r10_stage<20000, 2000>(Z, tws, t); __syncthreads();
    r10_stage< 2000,  200>(Z, tws, t); __syncthreads();
    r10_stage<  200,   20>(Z, tws, t); __syncthreads();
    r10_stage<   20,    2>(Z, tws, t); __syncthreads();
    for (int g = t; g < 10000; g += 1024) {           // radix-2 final stage
        float2 c0 = Z[2 * g], c1 = Z[2 * g + 1];
        Z[2 * g]     = make_float2(c0.x + c1.x, c0.y + c1.y);
        Z[2 * g + 1] = make_float2(c0.x - c1.x, c0.y - c1.y);
    }
    __syncthreads();

    // unpack conjugate-symmetric pair + log1p(|.|) + squared norms
    float* ha = g_h + (size_t)(2 * p) * NF;
    float* hb = ha + NF;
    float na = 0.f, nb = 0.f;
    for (int k = t; k < NF; k += 1024) {
        float va, vb;
        if (k == 0) { va = 0.f; vb = 0.f; }
        else {
            float2 zk = Z[posidx(k)];
            float2 zr = Z[posidx(20000 - k)];
            float are = 0.5f * (zk.x + zr.x), aim = 0.5f * (zk.y - zr.y);
            float bre = 0.5f * (zk.y + zr.y), bim = 0.5f * (zr.x - zk.x);
            va = log1pf(sqrtf(fmaf(are, are, aim * aim)));
            vb = log1pf(sqrtf(fmaf(bre, bre, bim * bim)));
        }
        ha[k] = va; hb[k] = vb;
        na = fmaf(va, va, na); nb = fmaf(vb, vb, nb);
    }
    #pragma unroll
    for (int off = 16; off > 0; off >>= 1) {
        na += __shfl_down_sync(0xffffffffu, na, off);
        nb += __shfl_down_sync(0xffffffffu, nb, off);
    }
    int wid = t >> 5, lane = t & 31;
    if (lane == 0) { sred[wid] = na; sred[32 + wid] = nb; }
    __syncthreads();
    if (t == 0) {
        float s1 = 0.f, s2 = 0.f;
        for (int i = 0; i < 32; i++) { s1 += sred[i]; s2 += sred[32 + i]; }
        g_invn0[2 * p]     = 1.0f / (sqrtf(s1) + 1e-8f);
        g_invn0[2 * p + 1] = 1.0f / (sqrtf(s2) + 1e-8f);
    }
}

// ------------- dual GEMM: Y = A W^T,  P = (A∘A) S^T  (64x64 tile, split-K) ------
__global__ void __launch_bounds__(256) gemm_dual_k(
    const float* __restrict__ A, const float* __restrict__ W, const float* __restrict__ S,
    float* __restrict__ Yp, float* __restrict__ Pp, int M, int N, int K, int Kc)
{
    __shared__ float sA[16][68], sW[16][68], sS[16][68];
    int t = threadIdx.x;
    int tx = t & 15, ty = t >> 4;
    int m0 = blockIdx.y * 64, n0 = blockIdx.x * 64;
    int z = blockIdx.z;
    int kbeg = z * Kc, kend = min(K, kbeg + Kc);
    float y[4][4] = {}, pq[4][4] = {};

    for (int k0 = kbeg; k0 < kend; k0 += 16) {
        #pragma unroll
        for (int i = 0; i < 4; i++) {
            int e = t + i * 256;
            int row = e >> 4, kk = e & 15;
            int gk = k0 + kk;
            bool ok = gk < kend;
            sA[kk][row] = ok ? A[(size_t)(m0 + row) * K + gk] : 0.f;
            sW[kk][row] = ok ? W[(size_t)(n0 + row) * K + gk] : 0.f;
            sS[kk][row] = ok ? S[(size_t)(n0 + row) * K + gk] : 0.f;
        }
        __syncthreads();
        #pragma unroll
        for (int kk = 0; kk < 16; kk++) {
            float av[4], wv[4], sv[4];
            #pragma unroll
            for (int i = 0; i < 4; i++) {
                av[i] = sA[kk][ty * 4 + i];
                wv[i] = sW[kk][tx * 4 + i];
                sv[i] = sS[kk][tx * 4 + i];
            }
            #pragma unroll
            for (int i = 0; i < 4; i++) {
                float a2 = av[i] * av[i];
                #pragma unroll
                for (int j = 0; j < 4; j++) {
                    y[i][j]  = fmaf(av[i], wv[j], y[i][j]);
                    pq[i][j] = fmaf(a2,    sv[j], pq[i][j]);
                }
            }
        }
        __syncthreads();
    }
    float* Yo = Yp + (size_t)z * M * N;
    float* Po = Pp + (size_t)z * M * N;
    #pragma unroll
    for (int i = 0; i < 4; i++)
        #pragma unroll
        for (int j = 0; j < 4; j++) {
            size_t off = (size_t)(m0 + ty * 4 + i) * N + (n0 + tx * 4 + j);
            Yo[off] = y[i][j]; Po[off] = pq[i][j];
        }
}

// ------------- epilogue: sum split-K partials + plastic + LN + GELU + norm ------
__global__ void epi_k(const float* __restrict__ Yp, const float* __restrict__ Pp,
                      const float* __restrict__ b, const float* __restrict__ eta,
                      const float* __restrict__ g, const float* __restrict__ be,
                      const float* __restrict__ invn_in,
                      float* __restrict__ act, float* __restrict__ invn_out, int H)
{
    __shared__ float sb[256];
    int r = blockIdx.x, o = threadIdx.x;
    size_t MN = (size_t)NB * H;
    size_t off = (size_t)r * H + o;
    float ys = b[o], pv = 0.f;
    #pragma unroll
    for (int s = 0; s < NSPLIT; s++) { ys += Yp[s * MN + off]; pv += Pp[s * MN + off]; }
    float y = fmaf(eta[0] * tanhf(ys), invn_in[r] * pv, ys);
    float invH = 1.0f / (float)H;
    float s1 = blockReduce(y, sb, o, H);
    float s2 = blockReduce(y * y, sb, o, H);
    float mu = s1 * invH;
    float var = fmaf(s2, invH, -mu * mu);
    float ln = (y - mu) * rsqrtf(var + 1e-5f) * g[o] + be[o];
    float a = 0.5f * ln * (1.0f + erff(ln * 0.70710678118654752f));
    act[off] = a;
    float s3 = blockReduce(a * a, sb, o, H);
    if (o == 0) invn_out[r] = 1.0f / (sqrtf(s3) + 1e-8f);
}

// ------------- head -------------
__global__ void head_k(const float* __restrict__ act, const float* __restrict__ hw,
                       const float* __restrict__ hb, float* __restrict__ out)
{
    int t = threadIdx.x;
    int warp = t >> 5, lane = t & 31;
    int r = blockIdx.x * 32 + warp;
    const float* a = act + (size_t)r * 64;
    float v = fmaf(a[lane], hw[lane], a[lane + 32] * hw[lane + 32]);
    #pragma unroll
    for (int off = 16; off > 0; off >>= 1) v += __shfl_down_sync(0xffffffffu, v, off);
    if (lane == 0) out[r] = v + hb[0];
}

// ---------------- host launch ----------------
extern "C" void kernel_launch(void* const* d_in, const int* in_sizes, int n_in,
                              void* d_out, int out_size)
{
    (void)in_sizes; (void)n_in; (void)out_size;
    const float* x    = (const float*)d_in[0];
    const float* W0   = (const float*)d_in[1];
    const float* al0  = (const float*)d_in[2];
    const float* b0   = (const float*)d_in[3];
    const float* eta0 = (const float*)d_in[4];
    const float* g0   = (const float*)d_in[5];
    const float* be0  = (const float*)d_in[6];
    const float* W1   = (const float*)d_in[7];
    const float* al1  = (const float*)d_in[8];
    const float* b1   = (const float*)d_in[9];
    const float* eta1 = (const float*)d_in[10];
    const float* g1   = (const float*)d_in[11];
    const float* be1  = (const float*)d_in[12];
    const float* W2   = (const float*)d_in[13];
    const float* al2  = (const float*)d_in[14];
    const float* b2   = (const float*)d_in[15];
    const float* eta2 = (const float*)d_in[16];
    const float* g2   = (const float*)d_in[17];
    const float* be2  = (const float*)d_in[18];
    const float* hw   = (const float*)d_in[19];
    const float* hb   = (const float*)d_in[20];
    float* out = (float*)d_out;

    float *pS0, *pS1, *pS2, *ph, *pYp, *pPp, *pa1, *pa2, *pa3, *pi0, *pi1, *pi2, *pi3;
    cudaGetSymbolAddress((void**)&pS0, g_S0);
    cudaGetSymbolAddress((void**)&pS1, g_S1);
    cudaGetSymbolAddress((void**)&pS2, g_S2);
    cudaGetSymbolAddress((void**)&ph,  g_h);
    cudaGetSymbolAddress((void**)&pYp, g_Yp);
    cudaGetSymbolAddress((void**)&pPp, g_Pp);
    cudaGetSymbolAddress((void**)&pa1, g_act1);
    cudaGetSymbolAddress((void**)&pa2, g_act2);
    cudaGetSymbolAddress((void**)&pa3, g_act3);
    cudaGetSymbolAddress((void**)&pi0, g_invn0);
    cudaGetSymbolAddress((void**)&pi1, g_invn1);
    cudaGetSymbolAddress((void**)&pi2, g_invn2);
    cudaGetSymbolAddress((void**)&pi3, g_invn3);

    const int SMEM_FFT = (20000 + 2000) * (int)sizeof(float2);  // 176000 B
    cudaFuncSetAttribute(fft_k, cudaFuncAttributeMaxDynamicSharedMemorySize, SMEM_FFT);

    twiddle_init_k<<<8, 256>>>();
    sigmoid_k<<<512, 256>>>(al0, pS0, 256 * NF);
    sigmoid_k<<<64, 256>>>(al1, pS1, 128 * 256);
    sigmoid_k<<<16, 256>>>(al2, pS2, 64 * 128);

    fft_k<<<NPAIR, 1024, SMEM_FFT>>>(x);

    // split-K chunk sizes (multiple of 16)
    int Kc0 = ((NF  + NSPLIT * 16 - 1) / (NSPLIT * 16)) * 16;  // 2512
    int Kc1 = ((256 + NSPLIT * 16 - 1) / (NSPLIT * 16)) * 16;  // 64
    int Kc2 = ((128 + NSPLIT * 16 - 1) / (NSPLIT * 16)) * 16;  // 32

    gemm_dual_k<<<dim3(256 / 64, NB / 64, NSPLIT), 256>>>(ph,  W0, pS0, pYp, pPp, NB, 256, NF,  Kc0);
    epi_k<<<NB, 256>>>(pYp, pPp, b0, eta0, g0, be0, pi0, pa1, pi1, 256);
    gemm_dual_k<<<dim3(128 / 64, NB / 64, NSPLIT), 256>>>(pa1, W1, pS1, pYp, pPp, NB, 128, 256, Kc1);
    epi_k<<<NB, 128>>>(pYp, pPp, b1, eta1, g1, be1, pi1, pa2, pi2, 128);
    gemm_dual_k<<<dim3(64 / 64,  NB / 64, NSPLIT), 256>>>(pa2, W2, pS2, pYp, pPp, NB, 64, 128,  Kc2);
    epi_k<<<NB, 64>>>(pYp, pPp, b2, eta2, g2, be2, pi2, pa3, pi3, 64);
    head_k<<<NB / 32, 1024>>>(pa3, hw, hb, out);
}

// round 6
// speedup vs baseline: 2.6258x; 1.0003x over previous
#include <cuda_runtime.h>
#include <math.h>

#define NB     1024
#define NCP    20000
#define NF     10001
#define NPAIR  512
#define NSPLIT 4

// ---------------- device scratch (no allocations allowed) ----------------
__device__ float  g_h[NB * NF];
__device__ float  g_S0[256 * NF];
__device__ float  g_S1[128 * 256];
__device__ float  g_S2[64 * 128];
__device__ float  g_invn0[NB];
__device__ float  g_invn1[NB];
__device__ float  g_invn2[NB];
__device__ float  g_invn3[NB];
__device__ float  g_Yp[NSPLIT * NB * 256];
__device__ float  g_Pp[NSPLIT * NB * 256];
__device__ float  g_act1[NB * 256];
__device__ float  g_act2[NB * 128];
__device__ float  g_act3[NB * 64];
__device__ float2 g_w20000[2000];   // only indices < 2000 are ever used

// ---------------- helpers ----------------
__device__ __forceinline__ float2 cmul(float2 a, float2 b) {
    return make_float2(a.x * b.x - a.y * b.y, a.x * b.y + a.y * b.x);
}
__device__ __forceinline__ float blockReduce(float v, float* sb, int tid, int n) {
    sb[tid] = v; __syncthreads();
    for (int s = n >> 1; s > 0; s >>= 1) {
        if (tid < s) sb[tid] += sb[tid + s];
        __syncthreads();
    }
    float r = sb[0]; __syncthreads();
    return r;
}

// digit-reversed position after DIF radix sequence [10,10,10,10,2]
__device__ __forceinline__ int posidx(int k) {
    int d0 = k % 10; k /= 10;
    int d1 = k % 10; k /= 10;
    int d2 = k % 10; k /= 10;
    int d3 = k % 10; int d4 = k / 10;
    return d0 * 2000 + d1 * 200 + d2 * 20 + d3 * 2 + d4;
}

// ---------------- init kernels ----------------
__global__ void twiddle_init_k() {
    int i = blockIdx.x * blockDim.x + threadIdx.x;
    if (i < 2000) {
        double s, c; sincospi(-2.0 * (double)i / 20000.0, &s, &c);
        g_w20000[i] = make_float2((float)c, (float)s);
    }
}

__global__ void sigmoid_k(const float* __restrict__ a, float* __restrict__ s, int n) {
    for (int i = blockIdx.x * blockDim.x + threadIdx.x; i < n; i += gridDim.x * blockDim.x)
        s[i] = 1.0f / (1.0f + expf(-a[i]));
}

// ---------------- radix-10 in-place DIF stage (sub-size NN, stride MM=NN/10) ----
template<int NN, int MM>
__device__ __forceinline__ void r10_stage(float2* Z, const float2* tws, int t)
{
    constexpr float WR[10] = { 1.f,  0.8090169943749475f,  0.30901699437494745f,
                              -0.30901699437494745f, -0.8090169943749475f, -1.f,
                              -0.8090169943749475f, -0.30901699437494745f,
                               0.30901699437494745f,  0.8090169943749475f };
    constexpr float WI[10] = { 0.f, -0.5877852522924731f, -0.9510565162951535f,
                              -0.9510565162951535f, -0.5877852522924731f,  0.f,
                               0.5877852522924731f,  0.9510565162951535f,
                               0.9510565162951535f,  0.5877852522924731f };
    for (int g = t; g < 2000; g += 1024) {
        int blk = g / MM, j = g - blk * MM;
        int base = blk * NN + j;
        float2 c[10];
        #pragma unroll
        for (int u = 0; u < 10; u++) c[u] = Z[base + u * MM];
        float2 w1 = tws[(20000 / NN) * j];
        // v = 0: plain sum
        float sx = c[0].x, sy = c[0].y;
        #pragma unroll
        for (int u = 1; u < 10; u++) { sx += c[u].x; sy += c[u].y; }
        float2 tw = w1;
        #pragma unroll
        for (int v = 1; v < 10; v++) {
            float ax = c[0].x, ay = c[0].y;
            #pragma unroll
            for (int u = 1; u < 10; u++) {
                const int idx = (u * v) % 10;   // compile-time after unroll
                ax = fmaf(c[u].x, WR[idx], ax); ax = fmaf(-c[u].y, WI[idx], ax);
                ay = fmaf(c[u].x, WI[idx], ay); ay = fmaf( c[u].y, WR[idx], ay);
            }
            Z[base + v * MM] = make_float2(ax * tw.x - ay * tw.y,
                                           ax * tw.y + ay * tw.x);
            tw = cmul(tw, w1);
        }
        Z[base] = make_float2(sx, sy);
    }
}

// ---------- fused FFT (packed 2 rows) + unpack + log1p|.| + row norms ----------
// mean subtraction only changes bin 0 of the FFT (constant offset), so we FFT raw
// x and force h[...,0] = 0 (reference gets ~1e-5 there; weight 0.01 -> negligible).
__global__ void __launch_bounds__(1024, 1) fft_k(const float* __restrict__ x)
{
    extern __shared__ float2 sm[];
    float2* Z   = sm;           // 20000 complex, in-place FFT
    float2* tws = sm + 20000;   // 2000 twiddles
    __shared__ float sred[64];
    int p = blockIdx.x, t = threadIdx.x;
    const float* xa = x + (size_t)(2 * p) * NCP;
    const float* xb = xa + NCP;
    for (int i = t; i < NCP; i += 1024) Z[i] = make_float2(xa[i], xb[i]);
    for (int i = t; i < 2000; i += 1024) tws[i] = g_w20000[i];
    __syncthreads();

    r10_stage<20000, 2000>(Z, tws, t); __syncthreads();
    r10_stage< 2000,  200>(Z, tws, t); __syncthreads();
    r10_stage<  200,   20>(Z, tws, t); __syncthreads();
    r10_stage<   20,    2>(Z, tws, t); __syncthreads();
    for (int g = t; g < 10000; g += 1024) {           // radix-2 final stage
        float2 c0 = Z[2 * g], c1 = Z[2 * g + 1];
        Z[2 * g]     = make_float2(c0.x + c1.x, c0.y + c1.y);
        Z[2 * g + 1] = make_float2(c0.x - c1.x, c0.y - c1.y);
    }
    __syncthreads();

    // unpack conjugate-symmetric pair + log1p(|.|) + squared norms
    float* ha = g_h + (size_t)(2 * p) * NF;
    float* hb = ha + NF;
    float na = 0.f, nb = 0.f;
    for (int k = t; k < NF; k += 1024) {
        float va, vb;
        if (k == 0) { va = 0.f; vb = 0.f; }
        else {
            float2 zk = Z[posidx(k)];
            float2 zr = Z[posidx(20000 - k)];
            float are = 0.5f * (zk.x + zr.x), aim = 0.5f * (zk.y - zr.y);
            float bre = 0.5f * (zk.y + zr.y), bim = 0.5f * (zr.x - zk.x);
            va = log1pf(sqrtf(fmaf(are, are, aim * aim)));
            vb = log1pf(sqrtf(fmaf(bre, bre, bim * bim)));
        }
        ha[k] = va; hb[k] = vb;
        na = fmaf(va, va, na); nb = fmaf(vb, vb, nb);
    }
    #pragma unroll
    for (int off = 16; off > 0; off >>= 1) {
        na += __shfl_down_sync(0xffffffffu, na, off);
        nb += __shfl_down_sync(0xffffffffu, nb, off);
    }
    int wid = t >> 5, lane = t & 31;
    if (lane == 0) { sred[wid] = na; sred[32 + wid] = nb; }
    __syncthreads();
    if (t == 0) {
        float s1 = 0.f, s2 = 0.f;
        for (int i = 0; i < 32; i++) { s1 += sred[i]; s2 += sred[32 + i]; }
        g_invn0[2 * p]     = 1.0f / (sqrtf(s1) + 1e-8f);
        g_invn0[2 * p + 1] = 1.0f / (sqrtf(s2) + 1e-8f);
    }
}

// ------------- dual GEMM: Y = A W^T,  P = (A∘A) S^T  (64x64 tile, split-K) ------
__global__ void __launch_bounds__(256) gemm_dual_k(
    const float* __restrict__ A, const float* __restrict__ W, const float* __restrict__ S,
    float* __restrict__ Yp, float* __restrict__ Pp, int M, int N, int K, int Kc)
{
    __shared__ float sA[16][68], sW[16][68], sS[16][68];
    int t = threadIdx.x;
    int tx = t & 15, ty = t >> 4;
    int m0 = blockIdx.y * 64, n0 = blockIdx.x * 64;
    int z = blockIdx.z;
    int kbeg = z * Kc, kend = min(K, kbeg + Kc);
    float y[4][4] = {}, pq[4][4] = {};

    for (int k0 = kbeg; k0 < kend; k0 += 16) {
        #pragma unroll
        for (int i = 0; i < 4; i++) {
            int e = t + i * 256;
            int row = e >> 4, kk = e & 15;
            int gk = k0 + kk;
            bool ok = gk < kend;
            sA[kk][row] = ok ? A[(size_t)(m0 + row) * K + gk] : 0.f;
            sW[kk][row] = ok ? W[(size_t)(n0 + row) * K + gk] : 0.f;
            sS[kk][row] = ok ? S[(size_t)(n0 + row) * K + gk] : 0.f;
        }
        __syncthreads();
        #pragma unroll
        for (int kk = 0; kk < 16; kk++) {
            float av[4], wv[4], sv[4];
            #pragma unroll
            for (int i = 0; i < 4; i++) {
                av[i] = sA[kk][ty * 4 + i];
                wv[i] = sW[kk][tx * 4 + i];
                sv[i] = sS[kk][tx * 4 + i];
            }
            #pragma unroll
            for (int i = 0; i < 4; i++) {
                float a2 = av[i] * av[i];
                #pragma unroll
                for (int j = 0; j < 4; j++) {
                    y[i][j]  = fmaf(av[i], wv[j], y[i][j]);
                    pq[i][j] = fmaf(a2,    sv[j], pq[i][j]);
                }
            }
        }
        __syncthreads();
    }
    float* Yo = Yp + (size_t)z * M * N;
    float* Po = Pp + (size_t)z * M * N;
    #pragma unroll
    for (int i = 0; i < 4; i++)
        #pragma unroll
        for (int j = 0; j < 4; j++) {
            size_t off = (size_t)(m0 + ty * 4 + i) * N + (n0 + tx * 4 + j);
            Yo[off] = y[i][j]; Po[off] = pq[i][j];
        }
}

// ------------- epilogue: sum split-K partials + plastic + LN + GELU + norm ------
__global__ void epi_k(const float* __restrict__ Yp, const float* __restrict__ Pp,
                      const float* __restrict__ b, const float* __restrict__ eta,
                      const float* __restrict__ g, const float* __restrict__ be,
                      const float* __restrict__ invn_in,
                      float* __restrict__ act, float* __restrict__ invn_out, int H)
{
    __shared__ float sb[256];
    int r = blockIdx.x, o = threadIdx.x;
    size_t MN = (size_t)NB * H;
    size_t off = (size_t)r * H + o;
    float ys = b[o], pv = 0.f;
    #pragma unroll
    for (int s = 0; s < NSPLIT; s++) { ys += Yp[s * MN + off]; pv += Pp[s * MN + off]; }
    float y = fmaf(eta[0] * tanhf(ys), invn_in[r] * pv, ys);
    float invH = 1.0f / (float)H;
    float s1 = blockReduce(y, sb, o, H);
    float s2 = blockReduce(y * y, sb, o, H);
    float mu = s1 * invH;
    float var = fmaf(s2, invH, -mu * mu);
    float ln = (y - mu) * rsqrtf(var + 1e-5f) * g[o] + be[o];
    float a = 0.5f * ln * (1.0f + erff(ln * 0.70710678118654752f));
    act[off] = a;
    float s3 = blockReduce(a * a, sb, o, H);
    if (o == 0) invn_out[r] = 1.0f / (sqrtf(s3) + 1e-8f);
}

// ------------- head -------------
__global__ void head_k(const float* __restrict__ act, const float* __restrict__ hw,
                       const float* __restrict__ hb, float* __restrict__ out)
{
    int t = threadIdx.x;
    int warp = t >> 5, lane = t & 31;
    int r = blockIdx.x * 32 + warp;
    const float* a = act + (size_t)r * 64;
    float v = fmaf(a[lane], hw[lane], a[lane + 32] * hw[lane + 32]);
    #pragma unroll
    for (int off = 16; off > 0; off >>= 1) v += __shfl_down_sync(0xffffffffu, v, off);
    if (lane == 0) out[r] = v + hb[0];
}

// ---------------- host launch ----------------
extern "C" void kernel_launch(void* const* d_in, const int* in_sizes, int n_in,
                              void* d_out, int out_size)
{
    (void)in_sizes; (void)n_in; (void)out_size;
    const float* x    = (const float*)d_in[0];
    const float* W0   = (const float*)d_in[1];
    const float* al0  = (const float*)d_in[2];
    const float* b0   = (const float*)d_in[3];
    const float* eta0 = (const float*)d_in[4];
    const float* g0   = (const float*)d_in[5];
    const float* be0  = (const float*)d_in[6];
    const float* W1   = (const float*)d_in[7];
    const float* al1  = (const float*)d_in[8];
    const float* b1   = (const float*)d_in[9];
    const float* eta1 = (const float*)d_in[10];
    const float* g1   = (const float*)d_in[11];
    const float* be1  = (const float*)d_in[12];
    const float* W2   = (const float*)d_in[13];
    const float* al2  = (const float*)d_in[14];
    const float* b2   = (const float*)d_in[15];
    const float* eta2 = (const float*)d_in[16];
    const float* g2   = (const float*)d_in[17];
    const float* be2  = (const float*)d_in[18];
    const float* hw   = (const float*)d_in[19];
    const float* hb   = (const float*)d_in[20];
    float* out = (float*)d_out;

    float *pS0, *pS1, *pS2, *ph, *pYp, *pPp, *pa1, *pa2, *pa3, *pi0, *pi1, *pi2, *pi3;
    cudaGetSymbolAddress((void**)&pS0, g_S0);
    cudaGetSymbolAddress((void**)&pS1, g_S1);
    cudaGetSymbolAddress((void**)&pS2, g_S2);
    cudaGetSymbolAddress((void**)&ph,  g_h);
    cudaGetSymbolAddress((void**)&pYp, g_Yp);
    cudaGetSymbolAddress((void**)&pPp, g_Pp);
    cudaGetSymbolAddress((void**)&pa1, g_act1);
    cudaGetSymbolAddress((void**)&pa2, g_act2);
    cudaGetSymbolAddress((void**)&pa3, g_act3);
    cudaGetSymbolAddress((void**)&pi0, g_invn0);
    cudaGetSymbolAddress((void**)&pi1, g_invn1);
    cudaGetSymbolAddress((void**)&pi2, g_invn2);
    cudaGetSymbolAddress((void**)&pi3, g_invn3);

    const int SMEM_FFT = (20000 + 2000) * (int)sizeof(float2);  // 176000 B
    cudaFuncSetAttribute(fft_k, cudaFuncAttributeMaxDynamicSharedMemorySize, SMEM_FFT);

    twiddle_init_k<<<8, 256>>>();
    sigmoid_k<<<512, 256>>>(al0, pS0, 256 * NF);
    sigmoid_k<<<64, 256>>>(al1, pS1, 128 * 256);
    sigmoid_k<<<16, 256>>>(al2, pS2, 64 * 128);

    fft_k<<<NPAIR, 1024, SMEM_FFT>>>(x);

    // split-K chunk sizes (multiple of 16)
    int Kc0 = ((NF  + NSPLIT * 16 - 1) / (NSPLIT * 16)) * 16;  // 2512
    int Kc1 = ((256 + NSPLIT * 16 - 1) / (NSPLIT * 16)) * 16;  // 64
    int Kc2 = ((128 + NSPLIT * 16 - 1) / (NSPLIT * 16)) * 16;  // 32

    gemm_dual_k<<<dim3(256 / 64, NB / 64, NSPLIT), 256>>>(ph,  W0, pS0, pYp, pPp, NB, 256, NF,  Kc0);
    epi_k<<<NB, 256>>>(pYp, pPp, b0, eta0, g0, be0, pi0, pa1, pi1, 256);
    gemm_dual_k<<<dim3(128 / 64, NB / 64, NSPLIT), 256>>>(pa1, W1, pS1, pYp, pPp, NB, 128, 256, Kc1);
    epi_k<<<NB, 128>>>(pYp, pPp, b1, eta1, g1, be1, pi1, pa2, pi2, 128);
    gemm_dual_k<<<dim3(64 / 64,  NB / 64, NSPLIT), 256>>>(pa2, W2, pS2, pYp, pPp, NB, 64, 128,  Kc2);
    epi_k<<<NB, 64>>>(pYp, pPp, b2, eta2, g2, be2, pi2, pa3, pi3, 64);
    head_k<<<NB / 32, 1024>>>(pa3, hw, hb, out);
}

// round 8
// speedup vs baseline: 5.0425x; 1.9204x over previous
#include <cuda_runtime.h>
#include <cuda_bf16.h>
#include <math.h>
#include <stdint.h>

#define NB     1024
#define NCP    20000
#define NF     10001
#define NPAIR  512
#define KP     10240      // padded K for tensor GEMM
#define TSPLIT 8          // split-K for tensor layer-0 GEMM
#define NSPLIT 4          // split-K for SIMT layers 1,2

// ---------------- device scratch (no allocations allowed) ----------------
__device__ __nv_bfloat16 g_Ahi[(size_t)NB * KP];
__device__ __nv_bfloat16 g_Alo[(size_t)NB * KP];
__device__ __nv_bfloat16 g_A2h[(size_t)NB * KP];
__device__ __nv_bfloat16 g_Whi[(size_t)256 * KP];
__device__ __nv_bfloat16 g_Wlo[(size_t)256 * KP];
__device__ __nv_bfloat16 g_Shi[(size_t)256 * KP];
__device__ float  g_S1[128 * 256];
__device__ float  g_S2[64 * 128];
__device__ float  g_invn0[NB];
__device__ float  g_invn1[NB];
__device__ float  g_invn2[NB];
__device__ float  g_invn3[NB];
__device__ float  g_Yp[TSPLIT * NB * 256];
__device__ float  g_Pp[TSPLIT * NB * 256];
__device__ float  g_act1[NB * 256];
__device__ float  g_act2[NB * 128];
__device__ float  g_act3[NB * 64];
__device__ float2 g_w20000[2000];

// ---------------- math helpers ----------------
__device__ __forceinline__ float2 cmul(float2 a, float2 b) {
    return make_float2(a.x * b.x - a.y * b.y, a.x * b.y + a.y * b.x);
}
__device__ __forceinline__ float blockReduce(float v, float* sb, int tid, int n) {
    sb[tid] = v; __syncthreads();
    for (int s = n >> 1; s > 0; s >>= 1) {
        if (tid < s) sb[tid] += sb[tid + s];
        __syncthreads();
    }
    float r = sb[0]; __syncthreads();
    return r;
}
__device__ __forceinline__ int posidx(int k) {
    int d0 = k % 10; k /= 10;
    int d1 = k % 10; k /= 10;
    int d2 = k % 10; k /= 10;
    int d3 = k % 10; int d4 = k / 10;
    return d0 * 2000 + d1 * 200 + d2 * 20 + d3 * 2 + d4;
}

// mma.sync m16n8k16 bf16 (sm_80+ PTX; works on plain sm_103 target)
__device__ __forceinline__ void mma16816(float* d, const uint32_t* a, const uint32_t* b) {
    asm volatile(
        "mma.sync.aligned.m16n8k16.row.col.f32.bf16.bf16.f32 "
        "{%0,%1,%2,%3}, {%4,%5,%6,%7}, {%8,%9}, {%0,%1,%2,%3};"
        : "+f"(d[0]), "+f"(d[1]), "+f"(d[2]), "+f"(d[3])
        : "r"(a[0]), "r"(a[1]), "r"(a[2]), "r"(a[3]), "r"(b[0]), "r"(b[1]));
}

// ---------------- init kernels ----------------
__global__ void twiddle_init_k() {
    int i = blockIdx.x * blockDim.x + threadIdx.x;
    if (i < 2000) {
        double s, c; sincospi(-2.0 * (double)i / 20000.0, &s, &c);
        g_w20000[i] = make_float2((float)c, (float)s);
    }
}
__global__ void sigmoid_k(const float* __restrict__ a, float* __restrict__ s, int n) {
    for (int i = blockIdx.x * blockDim.x + threadIdx.x; i < n; i += gridDim.x * blockDim.x)
        s[i] = 1.0f / (1.0f + expf(-a[i]));
}
// W-side conversion: Whi/Wlo split + Shi = bf16(sigmoid(alpha)), zero-padded to KP
__global__ void convW_k(const float* __restrict__ W, const float* __restrict__ al) {
    for (size_t i = blockIdx.x * blockDim.x + threadIdx.x; i < (size_t)256 * KP;
         i += (size_t)gridDim.x * blockDim.x) {
        int n = (int)(i / KP), k = (int)(i - (size_t)n * KP);
        float w = 0.f, s = 0.f;
        if (k < NF) {
            w = W[(size_t)n * NF + k];
            s = 1.0f / (1.0f + expf(-al[(size_t)n * NF + k]));
        }
        __nv_bfloat16 hi = __float2bfloat16(w);
        g_Whi[i] = hi;
        g_Wlo[i] = __float2bfloat16(w - __bfloat162float(hi));
        g_Shi[i] = __float2bfloat16(s);
    }
}

// ---------------- radix-10 in-place DIF stage ----------------
template<int NN, int MM>
__device__ __forceinline__ void r10_stage(float2* Z, const float2* tws, int t)
{
    constexpr float WR[10] = { 1.f,  0.8090169943749475f,  0.30901699437494745f,
                              -0.30901699437494745f, -0.8090169943749475f, -1.f,
                              -0.8090169943749475f, -0.30901699437494745f,
                               0.30901699437494745f,  0.8090169943749475f };
    constexpr float WI[10] = { 0.f, -0.5877852522924731f, -0.9510565162951535f,
                              -0.9510565162951535f, -0.5877852522924731f,  0.f,
                               0.5877852522924731f,  0.9510565162951535f,
                               0.9510565162951535f,  0.5877852522924731f };
    for (int g = t; g < 2000; g += 1024) {
        int blk = g / MM, j = g - blk * MM;
        int base = blk * NN + j;
        float2 c[10];
        #pragma unroll
        for (int u = 0; u < 10; u++) c[u] = Z[base + u * MM];
        float2 w1 = tws[(20000 / NN) * j];
        float sx = c[0].x, sy = c[0].y;
        #pragma unroll
        for (int u = 1; u < 10; u++) { sx += c[u].x; sy += c[u].y; }
        float2 tw = w1;
        #pragma unroll
        for (int v = 1; v < 10; v++) {
            float ax = c[0].x, ay = c[0].y;
            #pragma unroll
            for (int u = 1; u < 10; u++) {
                const int idx = (u * v) % 10;
                ax = fmaf(c[u].x, WR[idx], ax); ax = fmaf(-c[u].y, WI[idx], ax);
                ay = fmaf(c[u].x, WI[idx], ay); ay = fmaf( c[u].y, WR[idx], ay);
            }
            Z[base + v * MM] = make_float2(ax * tw.x - ay * tw.y,
                                           ax * tw.y + ay * tw.x);
            tw = cmul(tw, w1);
        }
        Z[base] = make_float2(sx, sy);
    }
}

// ---- fused FFT (packed 2 rows) + unpack + log1p|.| + norms + bf16 split out ----
__global__ void __launch_bounds__(1024, 1) fft_k(const float* __restrict__ x)
{
    extern __shared__ float2 sm[];
    float2* Z   = sm;
    float2* tws = sm + 20000;
    __shared__ float sred[64];
    int p = blockIdx.x, t = threadIdx.x;
    const float* xa = x + (size_t)(2 * p) * NCP;
    const float* xb = xa + NCP;
    for (int i = t; i < NCP; i += 1024) Z[i] = make_float2(xa[i], xb[i]);
    for (int i = t; i < 2000; i += 1024) tws[i] = g_w20000[i];
    __syncthreads();

    r10_stage<20000, 2000>(Z, tws, t); __syncthreads();
    r10_stage< 2000,  200>(Z, tws, t); __syncthreads();
    r10_stage<  200,   20>(Z, tws, t); __syncthreads();
    r10_stage<   20,    2>(Z, tws, t); __syncthreads();
    for (int g = t; g < 10000; g += 1024) {
        float2 c0 = Z[2 * g], c1 = Z[2 * g + 1];
        Z[2 * g]     = make_float2(c0.x + c1.x, c0.y + c1.y);
        Z[2 * g + 1] = make_float2(c0.x - c1.x, c0.y - c1.y);
    }
    __syncthreads();

    size_t rowA = (size_t)(2 * p) * KP, rowB = rowA + KP;
    float na = 0.f, nb = 0.f;
    for (int k = t; k < NF; k += 1024) {
        float va, vb;
        if (k == 0) { va = 0.f; vb = 0.f; }
        else {
            float2 zk = Z[posidx(k)];
            float2 zr = Z[posidx(20000 - k)];
            float are = 0.5f * (zk.x + zr.x), aim = 0.5f * (zk.y - zr.y);
            float bre = 0.5f * (zk.y + zr.y), bim = 0.5f * (zr.x - zk.x);
            va = log1pf(sqrtf(fmaf(are, are, aim * aim)));
            vb = log1pf(sqrtf(fmaf(bre, bre, bim * bim)));
        }
        __nv_bfloat16 ha = __float2bfloat16(va), hb = __float2bfloat16(vb);
        g_Ahi[rowA + k] = ha;
        g_Ahi[rowB + k] = hb;
        g_Alo[rowA + k] = __float2bfloat16(va - __bfloat162float(ha));
        g_Alo[rowB + k] = __float2bfloat16(vb - __bfloat162float(hb));
        g_A2h[rowA + k] = __float2bfloat16(va * va);
        g_A2h[rowB + k] = __float2bfloat16(vb * vb);
        na = fmaf(va, va, na); nb = fmaf(vb, vb, nb);
    }
    for (int k = NF + t; k < KP; k += 1024) {
        __nv_bfloat16 z0 = __float2bfloat16(0.f);
        g_Ahi[rowA + k] = z0; g_Ahi[rowB + k] = z0;
        g_Alo[rowA + k] = z0; g_Alo[rowB + k] = z0;
        g_A2h[rowA + k] = z0; g_A2h[rowB + k] = z0;
    }
    #pragma unroll
    for (int off = 16; off > 0; off >>= 1) {
        na += __shfl_down_sync(0xffffffffu, na, off);
        nb += __shfl_down_sync(0xffffffffu, nb, off);
    }
    int wid = t >> 5, lane = t & 31;
    if (lane == 0) { sred[wid] = na; sred[32 + wid] = nb; }
    __syncthreads();
    if (t == 0) {
        float s1 = 0.f, s2 = 0.f;
        for (int i = 0; i < 32; i++) { s1 += sred[i]; s2 += sred[32 + i]; }
        g_invn0[2 * p]     = 1.0f / (sqrtf(s1) + 1e-8f);
        g_invn0[2 * p + 1] = 1.0f / (sqrtf(s2) + 1e-8f);
    }
}

// ------------- layer-0 dual GEMM via mma.sync bf16 (hi/lo split) -------------
// block 64x64 tile, BK=32, 128 threads (4 warps, 2x2), warp tile 32x32.
// grid: (256/64=4, 1024/64=16, TSPLIT)
#define SST 40   // smem row stride in bf16 (40*2=80B, 16B-aligned, conflict-free frags)
__global__ void __launch_bounds__(128, 3) tgemm0_k(float* __restrict__ Yp, float* __restrict__ Pp)
{
    __shared__ __nv_bfloat16 sm[6 * 64 * SST];
    __nv_bfloat16* sAhi = sm;
    __nv_bfloat16* sAlo = sm + 1 * 64 * SST;
    __nv_bfloat16* sA2  = sm + 2 * 64 * SST;
    __nv_bfloat16* sWhi = sm + 3 * 64 * SST;
    __nv_bfloat16* sWlo = sm + 4 * 64 * SST;
    __nv_bfloat16* sS   = sm + 5 * 64 * SST;

    int t = threadIdx.x, wid = t >> 5, lane = t & 31;
    int wm = wid & 1, wn = wid >> 1;          // 2x2 warps
    int n0 = blockIdx.x * 64, m0 = blockIdx.y * 64, z = blockIdx.z;
    int kbase = z * (KP / TSPLIT);            // 1280 per split

    const __nv_bfloat16* srcs[6] = { g_Ahi, g_Alo, g_A2h, g_Whi, g_Wlo, g_Shi };

    float yacc[2][4][4] = {};
    float pacc[2][4][4] = {};

    int q = lane & 3, gp = lane >> 2;

    for (int kb = 0; kb < (KP / TSPLIT) / 32; kb++) {
        int k0 = kbase + kb * 32;
        // load 6 tiles of 64 rows x 32 bf16 (each row = 4 uint4)
        #pragma unroll
        for (int e = t; e < 1536; e += 128) {
            int tile = e >> 8, v = e & 255;
            int r = v >> 2, c4 = v & 3;
            int grow = (tile < 3 ? m0 : n0) + r;
            const __nv_bfloat16* src = srcs[tile] + ((size_t)grow * KP + k0 + c4 * 8);
            uint4 val = *reinterpret_cast<const uint4*>(src);
            *reinterpret_cast<uint4*>(sm + tile * 64 * SST + r * SST + c4 * 8) = val;
        }
        __syncthreads();

        #pragma unroll
        for (int ks = 0; ks < 32; ks += 16) {
            // A fragments: 3 products x 2 m-tiles
            uint32_t fa[3][2][4];
            #pragma unroll
            for (int pr = 0; pr < 3; pr++) {
                const __nv_bfloat16* sa = sm + pr * 64 * SST;
                #pragma unroll
                for (int mt = 0; mt < 2; mt++) {
                    int row = wm * 32 + mt * 16 + gp;
                    int kk = ks + q * 2;
                    fa[pr][mt][0] = *reinterpret_cast<const uint32_t*>(sa + row * SST + kk);
                    fa[pr][mt][1] = *reinterpret_cast<const uint32_t*>(sa + (row + 8) * SST + kk);
                    fa[pr][mt][2] = *reinterpret_cast<const uint32_t*>(sa + row * SST + kk + 8);
                    fa[pr][mt][3] = *reinterpret_cast<const uint32_t*>(sa + (row + 8) * SST + kk + 8);
                }
            }
            // B fragments: 3 products x 4 n-tiles
            uint32_t fb[3][4][2];
            #pragma unroll
            for (int pr = 0; pr < 3; pr++) {
                const __nv_bfloat16* sb = sm + (3 + pr) * 64 * SST;
                #pragma unroll
                for (int nt = 0; nt < 4; nt++) {
                    int nrow = wn * 32 + nt * 8 + gp;
                    int kk = ks + q * 2;
                    fb[pr][nt][0] = *reinterpret_cast<const uint32_t*>(sb + nrow * SST + kk);
                    fb[pr][nt][1] = *reinterpret_cast<const uint32_t*>(sb + nrow * SST + kk + 8);
                }
            }
            #pragma unroll
            for (int mt = 0; mt < 2; mt++)
                #pragma unroll
                for (int nt = 0; nt < 4; nt++) {
                    mma16816(yacc[mt][nt], fa[0][mt], fb[0][nt]);  // Ahi*Whi
                    mma16816(yacc[mt][nt], fa[0][mt], fb[1][nt]);  // Ahi*Wlo
                    mma16816(yacc[mt][nt], fa[1][mt], fb[0][nt]);  // Alo*Whi
                    mma16816(pacc[mt][nt], fa[2][mt], fb[2][nt]);  // A2*S
                }
        }
        __syncthreads();
    }

    float* Yo = Yp + (size_t)z * NB * 256;
    float* Po = Pp + (size_t)z * NB * 256;
    #pragma unroll
    for (int mt = 0; mt < 2; mt++)
        #pragma unroll
        for (int nt = 0; nt < 4; nt++) {
            int row = m0 + wm * 32 + mt * 16 + gp;
            int col = n0 + wn * 32 + nt * 8 + q * 2;
            *reinterpret_cast<float2*>(Yo + (size_t)row * 256 + col) =
                make_float2(yacc[mt][nt][0], yacc[mt][nt][1]);
            *reinterpret_cast<float2*>(Yo + (size_t)(row + 8) * 256 + col) =
                make_float2(yacc[mt][nt][2], yacc[mt][nt][3]);
            *reinterpret_cast<float2*>(Po + (size_t)row * 256 + col) =
                make_float2(pacc[mt][nt][0], pacc[mt][nt][1]);
            *reinterpret_cast<float2*>(Po + (size_t)(row + 8) * 256 + col) =
                make_float2(pacc[mt][nt][2], pacc[mt][nt][3]);
        }
}

// ------------- SIMT dual GEMM (layers 1,2) -------------
__global__ void __launch_bounds__(256) gemm_dual_k(
    const float* __restrict__ A, const float* __restrict__ W, const float* __restrict__ S,
    float* __restrict__ Yp, float* __restrict__ Pp, int M, int N, int K, int Kc)
{
    __shared__ float sA[16][68], sW[16][68], sS[16][68];
    int t = threadIdx.x;
    int tx = t & 15, ty = t >> 4;
    int m0 = blockIdx.y * 64, n0 = blockIdx.x * 64;
    int z = blockIdx.z;
    int kbeg = z * Kc, kend = min(K, kbeg + Kc);
    float y[4][4] = {}, pq[4][4] = {};

    for (int k0 = kbeg; k0 < kend; k0 += 16) {
        #pragma unroll
        for (int i = 0; i < 4; i++) {
            int e = t + i * 256;
            int row = e >> 4, kk = e & 15;
            int gk = k0 + kk;
            bool ok = gk < kend;
            sA[kk][row] = ok ? A[(size_t)(m0 + row) * K + gk] : 0.f;
            sW[kk][row] = ok ? W[(size_t)(n0 + row) * K + gk] : 0.f;
            sS[kk][row] = ok ? S[(size_t)(n0 + row) * K + gk] : 0.f;
        }
        __syncthreads();
        #pragma unroll
        for (int kk = 0; kk < 16; kk++) {
            float av[4], wv[4], sv[4];
            #pragma unroll
            for (int i = 0; i < 4; i++) {
                av[i] = sA[kk][ty * 4 + i];
                wv[i] = sW[kk][tx * 4 + i];
                sv[i] = sS[kk][tx * 4 + i];
            }
            #pragma unroll
            for (int i = 0; i < 4; i++) {
                float a2 = av[i] * av[i];
                #pragma unroll
                for (int j = 0; j < 4; j++) {
                    y[i][j]  = fmaf(av[i], wv[j], y[i][j]);
                    pq[i][j] = fmaf(a2,    sv[j], pq[i][j]);
                }
            }
        }
        __syncthreads();
    }
    float* Yo = Yp + (size_t)z * M * N;
    float* Po = Pp + (size_t)z * M * N;
    #pragma unroll
    for (int i = 0; i < 4; i++)
        #pragma unroll
        for (int j = 0; j < 4; j++) {
            size_t off = (size_t)(m0 + ty * 4 + i) * N + (n0 + tx * 4 + j);
            Yo[off] = y[i][j]; Po[off] = pq[i][j];
        }
}

// ------------- epilogue -------------
__global__ void epi_k(const float* __restrict__ Yp, const float* __restrict__ Pp,
                      const float* __restrict__ b, const float* __restrict__ eta,
                      const float* __restrict__ g, const float* __restrict__ be,
                      const float* __restrict__ invn_in,
                      float* __restrict__ act, float* __restrict__ invn_out,
                      int H, int nsplit)
{
    __shared__ float sb[256];
    int r = blockIdx.x, o = threadIdx.x;
    size_t MN = (size_t)NB * H;
    size_t off = (size_t)r * H + o;
    float ys = b[o], pv = 0.f;
    for (int s = 0; s < nsplit; s++) { ys += Yp[s * MN + off]; pv += Pp[s * MN + off]; }
    float y = fmaf(eta[0] * tanhf(ys), invn_in[r] * pv, ys);
    float invH = 1.0f / (float)H;
    float s1 = blockReduce(y, sb, o, H);
    float s2 = blockReduce(y * y, sb, o, H);
    float mu = s1 * invH;
    float var = fmaf(s2, invH, -mu * mu);
    float ln = (y - mu) * rsqrtf(var + 1e-5f) * g[o] + be[o];
    float a = 0.5f * ln * (1.0f + erff(ln * 0.70710678118654752f));
    act[off] = a;
    float s3 = blockReduce(a * a, sb, o, H);
    if (o == 0) invn_out[r] = 1.0f / (sqrtf(s3) + 1e-8f);
}

// ------------- head -------------
__global__ void head_k(const float* __restrict__ act, const float* __restrict__ hw,
                       const float* __restrict__ hb, float* __restrict__ out)
{
    int t = threadIdx.x;
    int warp = t >> 5, lane = t & 31;
    int r = blockIdx.x * 32 + warp;
    const float* a = act + (size_t)r * 64;
    float v = fmaf(a[lane], hw[lane], a[lane + 32] * hw[lane + 32]);
    #pragma unroll
    for (int off = 16; off > 0; off >>= 1) v += __shfl_down_sync(0xffffffffu, v, off);
    if (lane == 0) out[r] = v + hb[0];
}

// ---------------- host launch ----------------
extern "C" void kernel_launch(void* const* d_in, const int* in_sizes, int n_in,
                              void* d_out, int out_size)
{
    (void)in_sizes; (void)n_in; (void)out_size;
    const float* x    = (const float*)d_in[0];
    const float* W0   = (const float*)d_in[1];
    const float* al0  = (const float*)d_in[2];
    const float* b0   = (const float*)d_in[3];
    const float* eta0 = (const float*)d_in[4];
    const float* g0   = (const float*)d_in[5];
    const float* be0  = (const float*)d_in[6];
    const float* W1   = (const float*)d_in[7];
    const float* al1  = (const float*)d_in[8];
    const float* b1   = (const float*)d_in[9];
    const float* eta1 = (const float*)d_in[10];
    const float* g1   = (const float*)d_in[11];
    const float* be1  = (const float*)d_in[12];
    const float* W2   = (const float*)d_in[13];
    const float* al2  = (const float*)d_in[14];
    const float* b2   = (const float*)d_in[15];
    const float* eta2 = (const float*)d_in[16];
    const float* g2   = (const float*)d_in[17];
    const float* be2  = (const float*)d_in[18];
    const float* hw   = (const float*)d_in[19];
    const float* hb   = (const float*)d_in[20];
    float* out = (float*)d_out;

    float *pS1, *pS2, *pYp, *pPp, *pa1, *pa2, *pa3, *pi0, *pi1, *pi2, *pi3;
    cudaGetSymbolAddress((void**)&pS1, g_S1);
    cudaGetSymbolAddress((void**)&pS2, g_S2);
    cudaGetSymbolAddress((void**)&pYp, g_Yp);
    cudaGetSymbolAddress((void**)&pPp, g_Pp);
    cudaGetSymbolAddress((void**)&pa1, g_act1);
    cudaGetSymbolAddress((void**)&pa2, g_act2);
    cudaGetSymbolAddress((void**)&pa3, g_act3);
    cudaGetSymbolAddress((void**)&pi0, g_invn0);
    cudaGetSymbolAddress((void**)&pi1, g_invn1);
    cudaGetSymbolAddress((void**)&pi2, g_invn2);
    cudaGetSymbolAddress((void**)&pi3, g_invn3);

    const int SMEM_FFT = (20000 + 2000) * (int)sizeof(float2);  // 176000 B
    cudaFuncSetAttribute(fft_k, cudaFuncAttributeMaxDynamicSharedMemorySize, SMEM_FFT);

    twiddle_init_k<<<8, 256>>>();
    sigmoid_k<<<64, 256>>>(al1, pS1, 128 * 256);
    sigmoid_k<<<16, 256>>>(al2, pS2, 64 * 128);
    convW_k<<<512, 256>>>(W0, al0);

    fft_k<<<NPAIR, 1024, SMEM_FFT>>>(x);

    tgemm0_k<<<dim3(4, 16, TSPLIT), 128>>>(pYp, pPp);
    epi_k<<<NB, 256>>>(pYp, pPp, b0, eta0, g0, be0, pi0, pa1, pi1, 256, TSPLIT);

    int Kc1 = ((256 + NSPLIT * 16 - 1) / (NSPLIT * 16)) * 16;  // 64
    int Kc2 = ((128 + NSPLIT * 16 - 1) / (NSPLIT * 16)) * 16;  // 32
    gemm_dual_k<<<dim3(128 / 64, NB / 64, NSPLIT), 256>>>(pa1, W1, pS1, pYp, pPp, NB, 128, 256, Kc1);
    epi_k<<<NB, 128>>>(pYp, pPp, b1, eta1, g1, be1, pi1, pa2, pi2, 128, NSPLIT);
    gemm_dual_k<<<dim3(64 / 64,  NB / 64, NSPLIT), 256>>>(pa2, W2, pS2, pYp, pPp, NB, 64, 128, Kc2);
    epi_k<<<NB, 64>>>(pYp, pPp, b2, eta2, g2, be2, pi2, pa3, pi3, 64, NSPLIT);
    head_k<<<NB / 32, 1024>>>(pa3, hw, hb, out);
}

// round 9
// speedup vs baseline: 5.0470x; 1.0009x over previous
#include <cuda_runtime.h>
#include <cuda_bf16.h>
#include <math.h>
#include <stdint.h>

#define NB     1024
#define NCP    20000
#define NF     10001
#define NPAIR  512
#define KP     10240      // padded K for tensor GEMM
#define TSPLIT 8          // split-K for tensor layer-0 GEMM
#define NSPLIT 4          // split-K for SIMT layers 1,2

// ---------------- device scratch (no allocations allowed) ----------------
__device__ __nv_bfloat16 g_Ahi[(size_t)NB * KP];
__device__ __nv_bfloat16 g_Alo[(size_t)NB * KP];
__device__ __nv_bfloat16 g_A2h[(size_t)NB * KP];
__device__ __nv_bfloat16 g_Whi[(size_t)256 * KP];
__device__ __nv_bfloat16 g_Wlo[(size_t)256 * KP];
__device__ __nv_bfloat16 g_Shi[(size_t)256 * KP];
__device__ float  g_S1[128 * 256];
__device__ float  g_S2[64 * 128];
__device__ float  g_invn0[NB];
__device__ float  g_invn1[NB];
__device__ float  g_invn2[NB];
__device__ float  g_invn3[NB];
__device__ float  g_Yp[TSPLIT * NB * 256];
__device__ float  g_Pp[TSPLIT * NB * 256];
__device__ float  g_act1[NB * 256];
__device__ float  g_act2[NB * 128];
__device__ float  g_act3[NB * 64];
__device__ float2 g_w20000[2000];

// ---------------- math helpers ----------------
__device__ __forceinline__ float2 cmul(float2 a, float2 b) {
    return make_float2(a.x * b.x - a.y * b.y, a.x * b.y + a.y * b.x);
}
__device__ __forceinline__ float blockReduce(float v, float* sb, int tid, int n) {
    sb[tid] = v; __syncthreads();
    for (int s = n >> 1; s > 0; s >>= 1) {
        if (tid < s) sb[tid] += sb[tid + s];
        __syncthreads();
    }
    float r = sb[0]; __syncthreads();
    return r;
}
__device__ __forceinline__ int posidx(int k) {
    int d0 = k % 10; k /= 10;
    int d1 = k % 10; k /= 10;
    int d2 = k % 10; k /= 10;
    int d3 = k % 10; int d4 = k / 10;
    return d0 * 2000 + d1 * 200 + d2 * 20 + d3 * 2 + d4;
}

// mma.sync m16n8k16 bf16 (sm_80+ PTX; works on plain sm_103 target)
__device__ __forceinline__ void mma16816(float* d, const uint32_t* a, const uint32_t* b) {
    asm volatile(
        "mma.sync.aligned.m16n8k16.row.col.f32.bf16.bf16.f32 "
        "{%0,%1,%2,%3}, {%4,%5,%6,%7}, {%8,%9}, {%0,%1,%2,%3};"
        : "+f"(d[0]), "+f"(d[1]), "+f"(d[2]), "+f"(d[3])
        : "r"(a[0]), "r"(a[1]), "r"(a[2]), "r"(a[3]), "r"(b[0]), "r"(b[1]));
}

// ---------------- init kernels ----------------
__global__ void twiddle_init_k() {
    int i = blockIdx.x * blockDim.x + threadIdx.x;
    if (i < 2000) {
        double s, c; sincospi(-2.0 * (double)i / 20000.0, &s, &c);
        g_w20000[i] = make_float2((float)c, (float)s);
    }
}
__global__ void sigmoid_k(const float* __restrict__ a, float* __restrict__ s, int n) {
    for (int i = blockIdx.x * blockDim.x + threadIdx.x; i < n; i += gridDim.x * blockDim.x)
        s[i] = 1.0f / (1.0f + expf(-a[i]));
}
// W-side conversion: Whi/Wlo split + Shi = bf16(sigmoid(alpha)), zero-padded to KP
__global__ void convW_k(const float* __restrict__ W, const float* __restrict__ al) {
    for (size_t i = blockIdx.x * blockDim.x + threadIdx.x; i < (size_t)256 * KP;
         i += (size_t)gridDim.x * blockDim.x) {
        int n = (int)(i / KP), k = (int)(i - (size_t)n * KP);
        float w = 0.f, s = 0.f;
        if (k < NF) {
            w = W[(size_t)n * NF + k];
            s = 1.0f / (1.0f + expf(-al[(size_t)n * NF + k]));
        }
        __nv_bfloat16 hi = __float2bfloat16(w);
        g_Whi[i] = hi;
        g_Wlo[i] = __float2bfloat16(w - __bfloat162float(hi));
        g_Shi[i] = __float2bfloat16(s);
    }
}

// ---------------- radix-10 in-place DIF stage ----------------
template<int NN, int MM>
__device__ __forceinline__ void r10_stage(float2* Z, const float2* tws, int t)
{
    constexpr float WR[10] = { 1.f,  0.8090169943749475f,  0.30901699437494745f,
                              -0.30901699437494745f, -0.8090169943749475f, -1.f,
                              -0.8090169943749475f, -0.30901699437494745f,
                               0.30901699437494745f,  0.8090169943749475f };
    constexpr float WI[10] = { 0.f, -0.5877852522924731f, -0.9510565162951535f,
                              -0.9510565162951535f, -0.5877852522924731f,  0.f,
                               0.5877852522924731f,  0.9510565162951535f,
                               0.9510565162951535f,  0.5877852522924731f };
    for (int g = t; g < 2000; g += 1024) {
        int blk = g / MM, j = g - blk * MM;
        int base = blk * NN + j;
        float2 c[10];
        #pragma unroll
        for (int u = 0; u < 10; u++) c[u] = Z[base + u * MM];
        float2 w1 = tws[(20000 / NN) * j];
        float sx = c[0].x, sy = c[0].y;
        #pragma unroll
        for (int u = 1; u < 10; u++) { sx += c[u].x; sy += c[u].y; }
        float2 tw = w1;
        #pragma unroll
        for (int v = 1; v < 10; v++) {
            float ax = c[0].x, ay = c[0].y;
            #pragma unroll
            for (int u = 1; u < 10; u++) {
                const int idx = (u * v) % 10;
                ax = fmaf(c[u].x, WR[idx], ax); ax = fmaf(-c[u].y, WI[idx], ax);
                ay = fmaf(c[u].x, WI[idx], ay); ay = fmaf( c[u].y, WR[idx], ay);
            }
            Z[base + v * MM] = make_float2(ax * tw.x - ay * tw.y,
                                           ax * tw.y + ay * tw.x);
            tw = cmul(tw, w1);
        }
        Z[base] = make_float2(sx, sy);
    }
}

// ---- fused FFT (packed 2 rows) + unpack + log1p|.| + norms + bf16 split out ----
__global__ void __launch_bounds__(1024, 1) fft_k(const float* __restrict__ x)
{
    extern __shared__ float2 sm[];
    float2* Z   = sm;
    float2* tws = sm + 20000;
    __shared__ float sred[64];
    int p = blockIdx.x, t = threadIdx.x;
    const float* xa = x + (size_t)(2 * p) * NCP;
    const float* xb = xa + NCP;
    for (int i = t; i < NCP; i += 1024) Z[i] = make_float2(xa[i], xb[i]);
    for (int i = t; i < 2000; i += 1024) tws[i] = g_w20000[i];
    __syncthreads();

    r10_stage<20000, 2000>(Z, tws, t); __syncthreads();
    r10_stage< 2000,  200>(Z, tws, t); __syncthreads();
    r10_stage<  200,   20>(Z, tws, t); __syncthreads();
    r10_stage<   20,    2>(Z, tws, t); __syncthreads();
    for (int g = t; g < 10000; g += 1024) {
        float2 c0 = Z[2 * g], c1 = Z[2 * g + 1];
        Z[2 * g]     = make_float2(c0.x + c1.x, c0.y + c1.y);
        Z[2 * g + 1] = make_float2(c0.x - c1.x, c0.y - c1.y);
    }
    __syncthreads();

    size_t rowA = (size_t)(2 * p) * KP, rowB = rowA + KP;
    float na = 0.f, nb = 0.f;
    for (int k = t; k < NF; k += 1024) {
        float va, vb;
        if (k == 0) { va = 0.f; vb = 0.f; }
        else {
            float2 zk = Z[posidx(k)];
            float2 zr = Z[posidx(20000 - k)];
            float are = 0.5f * (zk.x + zr.x), aim = 0.5f * (zk.y - zr.y);
            float bre = 0.5f * (zk.y + zr.y), bim = 0.5f * (zr.x - zk.x);
            va = log1pf(sqrtf(fmaf(are, are, aim * aim)));
            vb = log1pf(sqrtf(fmaf(bre, bre, bim * bim)));
        }
        __nv_bfloat16 ha = __float2bfloat16(va), hb = __float2bfloat16(vb);
        g_Ahi[rowA + k] = ha;
        g_Ahi[rowB + k] = hb;
        g_Alo[rowA + k] = __float2bfloat16(va - __bfloat162float(ha));
        g_Alo[rowB + k] = __float2bfloat16(vb - __bfloat162float(hb));
        g_A2h[rowA + k] = __float2bfloat16(va * va);
        g_A2h[rowB + k] = __float2bfloat16(vb * vb);
        na = fmaf(va, va, na); nb = fmaf(vb, vb, nb);
    }
    for (int k = NF + t; k < KP; k += 1024) {
        __nv_bfloat16 z0 = __float2bfloat16(0.f);
        g_Ahi[rowA + k] = z0; g_Ahi[rowB + k] = z0;
        g_Alo[rowA + k] = z0; g_Alo[rowB + k] = z0;
        g_A2h[rowA + k] = z0; g_A2h[rowB + k] = z0;
    }
    #pragma unroll
    for (int off = 16; off > 0; off >>= 1) {
        na += __shfl_down_sync(0xffffffffu, na, off);
        nb += __shfl_down_sync(0xffffffffu, nb, off);
    }
    int wid = t >> 5, lane = t & 31;
    if (lane == 0) { sred[wid] = na; sred[32 + wid] = nb; }
    __syncthreads();
    if (t == 0) {
        float s1 = 0.f, s2 = 0.f;
        for (int i = 0; i < 32; i++) { s1 += sred[i]; s2 += sred[32 + i]; }
        g_invn0[2 * p]     = 1.0f / (sqrtf(s1) + 1e-8f);
        g_invn0[2 * p + 1] = 1.0f / (sqrtf(s2) + 1e-8f);
    }
}

// ------------- layer-0 dual GEMM via mma.sync bf16 (hi/lo split) -------------
// block 64x64 tile, BK=32, 128 threads (4 warps, 2x2), warp tile 32x32.
// grid: (256/64=4, 1024/64=16, TSPLIT)
#define SST 40   // smem row stride in bf16 (40*2=80B, 16B-aligned, conflict-free frags)
__global__ void __launch_bounds__(128, 3) tgemm0_k(float* __restrict__ Yp, float* __restrict__ Pp)
{
    __shared__ __nv_bfloat16 sm[6 * 64 * SST];
    __nv_bfloat16* sAhi = sm;
    __nv_bfloat16* sAlo = sm + 1 * 64 * SST;
    __nv_bfloat16* sA2  = sm + 2 * 64 * SST;
    __nv_bfloat16* sWhi = sm + 3 * 64 * SST;
    __nv_bfloat16* sWlo = sm + 4 * 64 * SST;
    __nv_bfloat16* sS   = sm + 5 * 64 * SST;

    int t = threadIdx.x, wid = t >> 5, lane = t & 31;
    int wm = wid & 1, wn = wid >> 1;          // 2x2 warps
    int n0 = blockIdx.x * 64, m0 = blockIdx.y * 64, z = blockIdx.z;
    int kbase = z * (KP / TSPLIT);            // 1280 per split

    const __nv_bfloat16* srcs[6] = { g_Ahi, g_Alo, g_A2h, g_Whi, g_Wlo, g_Shi };

    float yacc[2][4][4] = {};
    float pacc[2][4][4] = {};

    int q = lane & 3, gp = lane >> 2;

    for (int kb = 0; kb < (KP / TSPLIT) / 32; kb++) {
        int k0 = kbase + kb * 32;
        // load 6 tiles of 64 rows x 32 bf16 (each row = 4 uint4)
        #pragma unroll
        for (int e = t; e < 1536; e += 128) {
            int tile = e >> 8, v = e & 255;
            int r = v >> 2, c4 = v & 3;
            int grow = (tile < 3 ? m0 : n0) + r;
            const __nv_bfloat16* src = srcs[tile] + ((size_t)grow * KP + k0 + c4 * 8);
            uint4 val = *reinterpret_cast<const uint4*>(src);
            *reinterpret_cast<uint4*>(sm + tile * 64 * SST + r * SST + c4 * 8) = val;
        }
        __syncthreads();

        #pragma unroll
        for (int ks = 0; ks < 32; ks += 16) {
            // A fragments: 3 products x 2 m-tiles
            uint32_t fa[3][2][4];
            #pragma unroll
            for (int pr = 0; pr < 3; pr++) {
                const __nv_bfloat16* sa = sm + pr * 64 * SST;
                #pragma unroll
                for (int mt = 0; mt < 2; mt++) {
                    int row = wm * 32 + mt * 16 + gp;
                    int kk = ks + q * 2;
                    fa[pr][mt][0] = *reinterpret_cast<const uint32_t*>(sa + row * SST + kk);
                    fa[pr][mt][1] = *reinterpret_cast<const uint32_t*>(sa + (row + 8) * SST + kk);
                    fa[pr][mt][2] = *reinterpret_cast<const uint32_t*>(sa + row * SST + kk + 8);
                    fa[pr][mt][3] = *reinterpret_cast<const uint32_t*>(sa + (row + 8) * SST + kk + 8);
                }
            }
            // B fragments: 3 products x 4 n-tiles
            uint32_t fb[3][4][2];
            #pragma unroll
            for (int pr = 0; pr < 3; pr++) {
                const __nv_bfloat16* sb = sm + (3 + pr) * 64 * SST;
                #pragma unroll
                for (int nt = 0; nt < 4; nt++) {
                    int nrow = wn * 32 + nt * 8 + gp;
                    int kk = ks + q * 2;
                    fb[pr][nt][0] = *reinterpret_cast<const uint32_t*>(sb + nrow * SST + kk);
                    fb[pr][nt][1] = *reinterpret_cast<const uint32_t*>(sb + nrow * SST + kk + 8);
                }
            }
            #pragma unroll
            for (int mt = 0; mt < 2; mt++)
                #pragma unroll
                for (int nt = 0; nt < 4; nt++) {
                    mma16816(yacc[mt][nt], fa[0][mt], fb[0][nt]);  // Ahi*Whi
                    mma16816(yacc[mt][nt], fa[0][mt], fb[1][nt]);  // Ahi*Wlo
                    mma16816(yacc[mt][nt], fa[1][mt], fb[0][nt]);  // Alo*Whi
                    mma16816(pacc[mt][nt], fa[2][mt], fb[2][nt]);  // A2*S
                }
        }
        __syncthreads();
    }

    float* Yo = Yp + (size_t)z * NB * 256;
    float* Po = Pp + (size_t)z * NB * 256;
    #pragma unroll
    for (int mt = 0; mt < 2; mt++)
        #pragma unroll
        for (int nt = 0; nt < 4; nt++) {
            int row = m0 + wm * 32 + mt * 16 + gp;
            int col = n0 + wn * 32 + nt * 8 + q * 2;
            *reinterpret_cast<float2*>(Yo + (size_t)row * 256 + col) =
                make_float2(yacc[mt][nt][0], yacc[mt][nt][1]);
            *reinterpret_cast<float2*>(Yo + (size_t)(row + 8) * 256 + col) =
                make_float2(yacc[mt][nt][2], yacc[mt][nt][3]);
            *reinterpret_cast<float2*>(Po + (size_t)row * 256 + col) =
                make_float2(pacc[mt][nt][0], pacc[mt][nt][1]);
            *reinterpret_cast<float2*>(Po + (size_t)(row + 8) * 256 + col) =
                make_float2(pacc[mt][nt][2], pacc[mt][nt][3]);
        }
}

// ------------- SIMT dual GEMM (layers 1,2) -------------
__global__ void __launch_bounds__(256) gemm_dual_k(
    const float* __restrict__ A, const float* __restrict__ W, const float* __restrict__ S,
    float* __restrict__ Yp, float* __restrict__ Pp, int M, int N, int K, int Kc)
{
    __shared__ float sA[16][68], sW[16][68], sS[16][68];
    int t = threadIdx.x;
    int tx = t & 15, ty = t >> 4;
    int m0 = blockIdx.y * 64, n0 = blockIdx.x * 64;
    int z = blockIdx.z;
    int kbeg = z * Kc, kend = min(K, kbeg + Kc);
    float y[4][4] = {}, pq[4][4] = {};

    for (int k0 = kbeg; k0 < kend; k0 += 16) {
        #pragma unroll
        for (int i = 0; i < 4; i++) {
            int e = t + i * 256;
            int row = e >> 4, kk = e & 15;
            int gk = k0 + kk;
            bool ok = gk < kend;
            sA[kk][row] = ok ? A[(size_t)(m0 + row) * K + gk] : 0.f;
            sW[kk][row] = ok ? W[(size_t)(n0 + row) * K + gk] : 0.f;
            sS[kk][row] = ok ? S[(size_t)(n0 + row) * K + gk] : 0.f;
        }
        __syncthreads();
        #pragma unroll
        for (int kk = 0; kk < 16; kk++) {
            float av[4], wv[4], sv[4];
            #pragma unroll
            for (int i = 0; i < 4; i++) {
                av[i] = sA[kk][ty * 4 + i];
                wv[i] = sW[kk][tx * 4 + i];
                sv[i] = sS[kk][tx * 4 + i];
            }
            #pragma unroll
            for (int i = 0; i < 4; i++) {
                float a2 = av[i] * av[i];
                #pragma unroll
                for (int j = 0; j < 4; j++) {
                    y[i][j]  = fmaf(av[i], wv[j], y[i][j]);
                    pq[i][j] = fmaf(a2,    sv[j], pq[i][j]);
                }
            }
        }
        __syncthreads();
    }
    float* Yo = Yp + (size_t)z * M * N;
    float* Po = Pp + (size_t)z * M * N;
    #pragma unroll
    for (int i = 0; i < 4; i++)
        #pragma unroll
        for (int j = 0; j < 4; j++) {
            size_t off = (size_t)(m0 + ty * 4 + i) * N + (n0 + tx * 4 + j);
            Yo[off] = y[i][j]; Po[off] = pq[i][j];
        }
}

// ------------- epilogue -------------
__global__ void epi_k(const float* __restrict__ Yp, const float* __restrict__ Pp,
                      const float* __restrict__ b, const float* __restrict__ eta,
                      const float* __restrict__ g, const float* __restrict__ be,
                      const float* __restrict__ invn_in,
                      float* __restrict__ act, float* __restrict__ invn_out,
                      int H, int nsplit)
{
    __shared__ float sb[256];
    int r = blockIdx.x, o = threadIdx.x;
    size_t MN = (size_t)NB * H;
    size_t off = (size_t)r * H + o;
    float ys = b[o], pv = 0.f;
    for (int s = 0; s < nsplit; s++) { ys += Yp[s * MN + off]; pv += Pp[s * MN + off]; }
    float y = fmaf(eta[0] * tanhf(ys), invn_in[r] * pv, ys);
    float invH = 1.0f / (float)H;
    float s1 = blockReduce(y, sb, o, H);
    float s2 = blockReduce(y * y, sb, o, H);
    float mu = s1 * invH;
    float var = fmaf(s2, invH, -mu * mu);
    float ln = (y - mu) * rsqrtf(var + 1e-5f) * g[o] + be[o];
    float a = 0.5f * ln * (1.0f + erff(ln * 0.70710678118654752f));
    act[off] = a;
    float s3 = blockReduce(a * a, sb, o, H);
    if (o == 0) invn_out[r] = 1.0f / (sqrtf(s3) + 1e-8f);
}

// ------------- head -------------
__global__ void head_k(const float* __restrict__ act, const float* __restrict__ hw,
                       const float* __restrict__ hb, float* __restrict__ out)
{
    int t = threadIdx.x;
    int warp = t >> 5, lane = t & 31;
    int r = blockIdx.x * 32 + warp;
    const float* a = act + (size_t)r * 64;
    float v = fmaf(a[lane], hw[lane], a[lane + 32] * hw[lane + 32]);
    #pragma unroll
    for (int off = 16; off > 0; off >>= 1) v += __shfl_down_sync(0xffffffffu, v, off);
    if (lane == 0) out[r] = v + hb[0];
}

// ---------------- host launch ----------------
extern "C" void kernel_launch(void* const* d_in, const int* in_sizes, int n_in,
                              void* d_out, int out_size)
{
    (void)in_sizes; (void)n_in; (void)out_size;
    const float* x    = (const float*)d_in[0];
    const float* W0   = (const float*)d_in[1];
    const float* al0  = (const float*)d_in[2];
    const float* b0   = (const float*)d_in[3];
    const float* eta0 = (const float*)d_in[4];
    const float* g0   = (const float*)d_in[5];
    const float* be0  = (const float*)d_in[6];
    const float* W1   = (const float*)d_in[7];
    const float* al1  = (const float*)d_in[8];
    const float* b1   = (const float*)d_in[9];
    const float* eta1 = (const float*)d_in[10];
    const float* g1   = (const float*)d_in[11];
    const float* be1  = (const float*)d_in[12];
    const float* W2   = (const float*)d_in[13];
    const float* al2  = (const float*)d_in[14];
    const float* b2   = (const float*)d_in[15];
    const float* eta2 = (const float*)d_in[16];
    const float* g2   = (const float*)d_in[17];
    const float* be2  = (const float*)d_in[18];
    const float* hw   = (const float*)d_in[19];
    const float* hb   = (const float*)d_in[20];
    float* out = (float*)d_out;

    float *pS1, *pS2, *pYp, *pPp, *pa1, *pa2, *pa3, *pi0, *pi1, *pi2, *pi3;
    cudaGetSymbolAddress((void**)&pS1, g_S1);
    cudaGetSymbolAddress((void**)&pS2, g_S2);
    cudaGetSymbolAddress((void**)&pYp, g_Yp);
    cudaGetSymbolAddress((void**)&pPp, g_Pp);
    cudaGetSymbolAddress((void**)&pa1, g_act1);
    cudaGetSymbolAddress((void**)&pa2, g_act2);
    cudaGetSymbolAddress((void**)&pa3, g_act3);
    cudaGetSymbolAddress((void**)&pi0, g_invn0);
    cudaGetSymbolAddress((void**)&pi1, g_invn1);
    cudaGetSymbolAddress((void**)&pi2, g_invn2);
    cudaGetSymbolAddress((void**)&pi3, g_invn3);

    const int SMEM_FFT = (20000 + 2000) * (int)sizeof(float2);  // 176000 B
    cudaFuncSetAttribute(fft_k, cudaFuncAttributeMaxDynamicSharedMemorySize, SMEM_FFT);

    twiddle_init_k<<<8, 256>>>();
    sigmoid_k<<<64, 256>>>(al1, pS1, 128 * 256);
    sigmoid_k<<<16, 256>>>(al2, pS2, 64 * 128);
    convW_k<<<512, 256>>>(W0, al0);

    fft_k<<<NPAIR, 1024, SMEM_FFT>>>(x);

    tgemm0_k<<<dim3(4, 16, TSPLIT), 128>>>(pYp, pPp);
    epi_k<<<NB, 256>>>(pYp, pPp, b0, eta0, g0, be0, pi0, pa1, pi1, 256, TSPLIT);

    int Kc1 = ((256 + NSPLIT * 16 - 1) / (NSPLIT * 16)) * 16;  // 64
    int Kc2 = ((128 + NSPLIT * 16 - 1) / (NSPLIT * 16)) * 16;  // 32
    gemm_dual_k<<<dim3(128 / 64, NB / 64, NSPLIT), 256>>>(pa1, W1, pS1, pYp, pPp, NB, 128, 256, Kc1);
    epi_k<<<NB, 128>>>(pYp, pPp, b1, eta1, g1, be1, pi1, pa2, pi2, 128, NSPLIT);
    gemm_dual_k<<<dim3(64 / 64,  NB / 64, NSPLIT), 256>>>(pa2, W2, pS2, pYp, pPp, NB, 64, 128, Kc2);
    epi_k<<<NB, 64>>>(pYp, pPp, b2, eta2, g2, be2, pi2, pa3, pi3, 64, NSPLIT);
    head_k<<<NB / 32, 1024>>>(pa3, hw, hb, out);
}

// round 10
// speedup vs baseline: 5.0511x; 1.0008x over previous
#include <cuda_runtime.h>
#include <cuda_bf16.h>
#include <math.h>
#include <stdint.h>

#define NB     1024
#define NCP    20000
#define NF     10001
#define NPAIR  512
#define KP     10240      // padded K for tensor GEMM
#define TSPLIT 8          // split-K for tensor layer-0 GEMM
#define NSPLIT 4          // split-K for SIMT layers 1,2

// ---------------- device scratch (no allocations allowed) ----------------
__device__ __nv_bfloat16 g_Ahi[(size_t)NB * KP];
__device__ __nv_bfloat16 g_Alo[(size_t)NB * KP];
__device__ __nv_bfloat16 g_A2h[(size_t)NB * KP];
__device__ __nv_bfloat16 g_Whi[(size_t)256 * KP];
__device__ __nv_bfloat16 g_Wlo[(size_t)256 * KP];
__device__ __nv_bfloat16 g_Shi[(size_t)256 * KP];
__device__ float  g_S1[128 * 256];
__device__ float  g_S2[64 * 128];
__device__ float  g_invn0[NB];
__device__ float  g_invn1[NB];
__device__ float  g_invn2[NB];
__device__ float  g_invn3[NB];
__device__ float  g_Yp[TSPLIT * NB * 256];
__device__ float  g_Pp[TSPLIT * NB * 256];
__device__ float  g_act1[NB * 256];
__device__ float  g_act2[NB * 128];
__device__ float  g_act3[NB * 64];
__device__ float2 g_w20000[2000];

// ---------------- math helpers ----------------
__device__ __forceinline__ float2 cmul(float2 a, float2 b) {
    return make_float2(a.x * b.x - a.y * b.y, a.x * b.y + a.y * b.x);
}
__device__ __forceinline__ float blockReduce(float v, float* sb, int tid, int n) {
    sb[tid] = v; __syncthreads();
    for (int s = n >> 1; s > 0; s >>= 1) {
        if (tid < s) sb[tid] += sb[tid + s];
        __syncthreads();
    }
    float r = sb[0]; __syncthreads();
    return r;
}
__device__ __forceinline__ int posidx(int k) {
    int d0 = k % 10; k /= 10;
    int d1 = k % 10; k /= 10;
    int d2 = k % 10; k /= 10;
    int d3 = k % 10; int d4 = k / 10;
    return d0 * 2000 + d1 * 200 + d2 * 20 + d3 * 2 + d4;
}

// mma.sync m16n8k16 bf16 (sm_80+ PTX; works on plain sm_103 target)
__device__ __forceinline__ void mma16816(float* d, const uint32_t* a, const uint32_t* b) {
    asm volatile(
        "mma.sync.aligned.m16n8k16.row.col.f32.bf16.bf16.f32 "
        "{%0,%1,%2,%3}, {%4,%5,%6,%7}, {%8,%9}, {%0,%1,%2,%3};"
        : "+f"(d[0]), "+f"(d[1]), "+f"(d[2]), "+f"(d[3])
        : "r"(a[0]), "r"(a[1]), "r"(a[2]), "r"(a[3]), "r"(b[0]), "r"(b[1]));
}

// ---------------- init kernels ----------------
__global__ void twiddle_init_k() {
    int i = blockIdx.x * blockDim.x + threadIdx.x;
    if (i < 2000) {
        double s, c; sincospi(-2.0 * (double)i / 20000.0, &s, &c);
        g_w20000[i] = make_float2((float)c, (float)s);
    }
}
__global__ void sigmoid_k(const float* __restrict__ a, float* __restrict__ s, int n) {
    for (int i = blockIdx.x * blockDim.x + threadIdx.x; i < n; i += gridDim.x * blockDim.x)
        s[i] = 1.0f / (1.0f + expf(-a[i]));
}
// W-side conversion: Whi/Wlo split + Shi = bf16(sigmoid(alpha)), zero-padded to KP
__global__ void convW_k(const float* __restrict__ W, const float* __restrict__ al) {
    for (size_t i = blockIdx.x * blockDim.x + threadIdx.x; i < (size_t)256 * KP;
         i += (size_t)gridDim.x * blockDim.x) {
        int n = (int)(i / KP), k = (int)(i - (size_t)n * KP);
        float w = 0.f, s = 0.f;
        if (k < NF) {
            w = W[(size_t)n * NF + k];
            s = 1.0f / (1.0f + expf(-al[(size_t)n * NF + k]));
        }
        __nv_bfloat16 hi = __float2bfloat16(w);
        g_Whi[i] = hi;
        g_Wlo[i] = __float2bfloat16(w - __bfloat162float(hi));
        g_Shi[i] = __float2bfloat16(s);
    }
}

// ---------------- radix-10 in-place DIF stage ----------------
template<int NN, int MM>
__device__ __forceinline__ void r10_stage(float2* Z, const float2* tws, int t)
{
    constexpr float WR[10] = { 1.f,  0.8090169943749475f,  0.30901699437494745f,
                              -0.30901699437494745f, -0.8090169943749475f, -1.f,
                              -0.8090169943749475f, -0.30901699437494745f,
                               0.30901699437494745f,  0.8090169943749475f };
    constexpr float WI[10] = { 0.f, -0.5877852522924731f, -0.9510565162951535f,
                              -0.9510565162951535f, -0.5877852522924731f,  0.f,
                               0.5877852522924731f,  0.9510565162951535f,
                               0.9510565162951535f,  0.5877852522924731f };
    for (int g = t; g < 2000; g += 1024) {
        int blk = g / MM, j = g - blk * MM;
        int base = blk * NN + j;
        float2 c[10];
        #pragma unroll
        for (int u = 0; u < 10; u++) c[u] = Z[base + u * MM];
        float2 w1 = tws[(20000 / NN) * j];
        float sx = c[0].x, sy = c[0].y;
        #pragma unroll
        for (int u = 1; u < 10; u++) { sx += c[u].x; sy += c[u].y; }
        float2 tw = w1;
        #pragma unroll
        for (int v = 1; v < 10; v++) {
            float ax = c[0].x, ay = c[0].y;
            #pragma unroll
            for (int u = 1; u < 10; u++) {
                const int idx = (u * v) % 10;
                ax = fmaf(c[u].x, WR[idx], ax); ax = fmaf(-c[u].y, WI[idx], ax);
                ay = fmaf(c[u].x, WI[idx], ay); ay = fmaf( c[u].y, WR[idx], ay);
            }
            Z[base + v * MM] = make_float2(ax * tw.x - ay * tw.y,
                                           ax * tw.y + ay * tw.x);
            tw = cmul(tw, w1);
        }
        Z[base] = make_float2(sx, sy);
    }
}

// ---- fused FFT (packed 2 rows) + unpack + log1p|.| + norms + bf16 split out ----
__global__ void __launch_bounds__(1024, 1) fft_k(const float* __restrict__ x)
{
    extern __shared__ float2 sm[];
    float2* Z   = sm;
    float2* tws = sm + 20000;
    __shared__ float sred[64];
    int p = blockIdx.x, t = threadIdx.x;
    const float* xa = x + (size_t)(2 * p) * NCP;
    const float* xb = xa + NCP;
    for (int i = t; i < NCP; i += 1024) Z[i] = make_float2(xa[i], xb[i]);
    for (int i = t; i < 2000; i += 1024) tws[i] = g_w20000[i];
    __syncthreads();

    r10_stage<20000, 2000>(Z, tws, t); __syncthreads();
    r10_stage< 2000,  200>(Z, tws, t); __syncthreads();
    r10_stage<  200,   20>(Z, tws, t); __syncthreads();
    r10_stage<   20,    2>(Z, tws, t); __syncthreads();
    for (int g = t; g < 10000; g += 1024) {
        float2 c0 = Z[2 * g], c1 = Z[2 * g + 1];
        Z[2 * g]     = make_float2(c0.x + c1.x, c0.y + c1.y);
        Z[2 * g + 1] = make_float2(c0.x - c1.x, c0.y - c1.y);
    }
    __syncthreads();

    size_t rowA = (size_t)(2 * p) * KP, rowB = rowA + KP;
    float na = 0.f, nb = 0.f;
    for (int k = t; k < NF; k += 1024) {
        float va, vb;
        if (k == 0) { va = 0.f; vb = 0.f; }
        else {
            float2 zk = Z[posidx(k)];
            float2 zr = Z[posidx(20000 - k)];
            float are = 0.5f * (zk.x + zr.x), aim = 0.5f * (zk.y - zr.y);
            float bre = 0.5f * (zk.y + zr.y), bim = 0.5f * (zr.x - zk.x);
            va = log1pf(sqrtf(fmaf(are, are, aim * aim)));
            vb = log1pf(sqrtf(fmaf(bre, bre, bim * bim)));
        }
        __nv_bfloat16 ha = __float2bfloat16(va), hb = __float2bfloat16(vb);
        g_Ahi[rowA + k] = ha;
        g_Ahi[rowB + k] = hb;
        g_Alo[rowA + k] = __float2bfloat16(va - __bfloat162float(ha));
        g_Alo[rowB + k] = __float2bfloat16(vb - __bfloat162float(hb));
        g_A2h[rowA + k] = __float2bfloat16(va * va);
        g_A2h[rowB + k] = __float2bfloat16(vb * vb);
        na = fmaf(va, va, na); nb = fmaf(vb, vb, nb);
    }
    for (int k = NF + t; k < KP; k += 1024) {
        __nv_bfloat16 z0 = __float2bfloat16(0.f);
        g_Ahi[rowA + k] = z0; g_Ahi[rowB + k] = z0;
        g_Alo[rowA + k] = z0; g_Alo[rowB + k] = z0;
        g_A2h[rowA + k] = z0; g_A2h[rowB + k] = z0;
    }
    #pragma unroll
    for (int off = 16; off > 0; off >>= 1) {
        na += __shfl_down_sync(0xffffffffu, na, off);
        nb += __shfl_down_sync(0xffffffffu, nb, off);
    }
    int wid = t >> 5, lane = t & 31;
    if (lane == 0) { sred[wid] = na; sred[32 + wid] = nb; }
    __syncthreads();
    if (t == 0) {
        float s1 = 0.f, s2 = 0.f;
        for (int i = 0; i < 32; i++) { s1 += sred[i]; s2 += sred[32 + i]; }
        g_invn0[2 * p]     = 1.0f / (sqrtf(s1) + 1e-8f);
        g_invn0[2 * p + 1] = 1.0f / (sqrtf(s2) + 1e-8f);
    }
}

// ------------- layer-0 dual GEMM via mma.sync bf16 (hi/lo split) -------------
// block 64x64 tile, BK=32, 128 threads (4 warps, 2x2), warp tile 32x32.
// grid: (256/64=4, 1024/64=16, TSPLIT)
#define SST 40   // smem row stride in bf16 (40*2=80B, 16B-aligned, conflict-free frags)
__global__ void __launch_bounds__(128, 3) tgemm0_k(float* __restrict__ Yp, float* __restrict__ Pp)
{
    __shared__ __nv_bfloat16 sm[6 * 64 * SST];
    __nv_bfloat16* sAhi = sm;
    __nv_bfloat16* sAlo = sm + 1 * 64 * SST;
    __nv_bfloat16* sA2  = sm + 2 * 64 * SST;
    __nv_bfloat16* sWhi = sm + 3 * 64 * SST;
    __nv_bfloat16* sWlo = sm + 4 * 64 * SST;
    __nv_bfloat16* sS   = sm + 5 * 64 * SST;

    int t = threadIdx.x, wid = t >> 5, lane = t & 31;
    int wm = wid & 1, wn = wid >> 1;          // 2x2 warps
    int n0 = blockIdx.x * 64, m0 = blockIdx.y * 64, z = blockIdx.z;
    int kbase = z * (KP / TSPLIT);            // 1280 per split

    const __nv_bfloat16* srcs[6] = { g_Ahi, g_Alo, g_A2h, g_Whi, g_Wlo, g_Shi };

    float yacc[2][4][4] = {};
    float pacc[2][4][4] = {};

    int q = lane & 3, gp = lane >> 2;

    for (int kb = 0; kb < (KP / TSPLIT) / 32; kb++) {
        int k0 = kbase + kb * 32;
        // load 6 tiles of 64 rows x 32 bf16 (each row = 4 uint4)
        #pragma unroll
        for (int e = t; e < 1536; e += 128) {
            int tile = e >> 8, v = e & 255;
            int r = v >> 2, c4 = v & 3;
            int grow = (tile < 3 ? m0 : n0) + r;
            const __nv_bfloat16* src = srcs[tile] + ((size_t)grow * KP + k0 + c4 * 8);
            uint4 val = *reinterpret_cast<const uint4*>(src);
            *reinterpret_cast<uint4*>(sm + tile * 64 * SST + r * SST + c4 * 8) = val;
        }
        __syncthreads();

        #pragma unroll
        for (int ks = 0; ks < 32; ks += 16) {
            // A fragments: 3 products x 2 m-tiles
            uint32_t fa[3][2][4];
            #pragma unroll
            for (int pr = 0; pr < 3; pr++) {
                const __nv_bfloat16* sa = sm + pr * 64 * SST;
                #pragma unroll
                for (int mt = 0; mt < 2; mt++) {
                    int row = wm * 32 + mt * 16 + gp;
                    int kk = ks + q * 2;
                    fa[pr][mt][0] = *reinterpret_cast<const uint32_t*>(sa + row * SST + kk);
                    fa[pr][mt][1] = *reinterpret_cast<const uint32_t*>(sa + (row + 8) * SST + kk);
                    fa[pr][mt][2] = *reinterpret_cast<const uint32_t*>(sa + row * SST + kk + 8);
                    fa[pr][mt][3] = *reinterpret_cast<const uint32_t*>(sa + (row + 8) * SST + kk + 8);
                }
            }
            // B fragments: 3 products x 4 n-tiles
            uint32_t fb[3][4][2];
            #pragma unroll
            for (int pr = 0; pr < 3; pr++) {
                const __nv_bfloat16* sb = sm + (3 + pr) * 64 * SST;
                #pragma unroll
                for (int nt = 0; nt < 4; nt++) {
                    int nrow = wn * 32 + nt * 8 + gp;
                    int kk = ks + q * 2;
                    fb[pr][nt][0] = *reinterpret_cast<const uint32_t*>(sb + nrow * SST + kk);
                    fb[pr][nt][1] = *reinterpret_cast<const uint32_t*>(sb + nrow * SST + kk + 8);
                }
            }
            #pragma unroll
            for (int mt = 0; mt < 2; mt++)
                #pragma unroll
                for (int nt = 0; nt < 4; nt++) {
                    mma16816(yacc[mt][nt], fa[0][mt], fb[0][nt]);  // Ahi*Whi
                    mma16816(yacc[mt][nt], fa[0][mt], fb[1][nt]);  // Ahi*Wlo
                    mma16816(yacc[mt][nt], fa[1][mt], fb[0][nt]);  // Alo*Whi
                    mma16816(pacc[mt][nt], fa[2][mt], fb[2][nt]);  // A2*S
                }
        }
        __syncthreads();
    }

    float* Yo = Yp + (size_t)z * NB * 256;
    float* Po = Pp + (size_t)z * NB * 256;
    #pragma unroll
    for (int mt = 0; mt < 2; mt++)
        #pragma unroll
        for (int nt = 0; nt < 4; nt++) {
            int row = m0 + wm * 32 + mt * 16 + gp;
            int col = n0 + wn * 32 + nt * 8 + q * 2;
            *reinterpret_cast<float2*>(Yo + (size_t)row * 256 + col) =
                make_float2(yacc[mt][nt][0], yacc[mt][nt][1]);
            *reinterpret_cast<float2*>(Yo + (size_t)(row + 8) * 256 + col) =
                make_float2(yacc[mt][nt][2], yacc[mt][nt][3]);
            *reinterpret_cast<float2*>(Po + (size_t)row * 256 + col) =
                make_float2(pacc[mt][nt][0], pacc[mt][nt][1]);
            *reinterpret_cast<float2*>(Po + (size_t)(row + 8) * 256 + col) =
                make_float2(pacc[mt][nt][2], pacc[mt][nt][3]);
        }
}

// ------------- SIMT dual GEMM (layers 1,2) -------------
__global__ void __launch_bounds__(256) gemm_dual_k(
    const float* __restrict__ A, const float* __restrict__ W, const float* __restrict__ S,
    float* __restrict__ Yp, float* __restrict__ Pp, int M, int N, int K, int Kc)
{
    __shared__ float sA[16][68], sW[16][68], sS[16][68];
    int t = threadIdx.x;
    int tx = t & 15, ty = t >> 4;
    int m0 = blockIdx.y * 64, n0 = blockIdx.x * 64;
    int z = blockIdx.z;
    int kbeg = z * Kc, kend = min(K, kbeg + Kc);
    float y[4][4] = {}, pq[4][4] = {};

    for (int k0 = kbeg; k0 < kend; k0 += 16) {
        #pragma unroll
        for (int i = 0; i < 4; i++) {
            int e = t + i * 256;
            int row = e >> 4, kk = e & 15;
            int gk = k0 + kk;
            bool ok = gk < kend;
            sA[kk][row] = ok ? A[(size_t)(m0 + row) * K + gk] : 0.f;
            sW[kk][row] = ok ? W[(size_t)(n0 + row) * K + gk] : 0.f;
            sS[kk][row] = ok ? S[(size_t)(n0 + row) * K + gk] : 0.f;
        }
        __syncthreads();
        #pragma unroll
        for (int kk = 0; kk < 16; kk++) {
            float av[4], wv[4], sv[4];
            #pragma unroll
            for (int i = 0; i < 4; i++) {
                av[i] = sA[kk][ty * 4 + i];
                wv[i] = sW[kk][tx * 4 + i];
                sv[i] = sS[kk][tx * 4 + i];
            }
            #pragma unroll
            for (int i = 0; i < 4; i++) {
                float a2 = av[i] * av[i];
                #pragma unroll
                for (int j = 0; j < 4; j++) {
                    y[i][j]  = fmaf(av[i], wv[j], y[i][j]);
                    pq[i][j] = fmaf(a2,    sv[j], pq[i][j]);
                }
            }
        }
        __syncthreads();
    }
    float* Yo = Yp + (size_t)z * M * N;
    float* Po = Pp + (size_t)z * M * N;
    #pragma unroll
    for (int i = 0; i < 4; i++)
        #pragma unroll
        for (int j = 0; j < 4; j++) {
            size_t off = (size_t)(m0 + ty * 4 + i) * N + (n0 + tx * 4 + j);
            Yo[off] = y[i][j]; Po[off] = pq[i][j];
        }
}

// ------------- epilogue -------------
__global__ void epi_k(const float* __restrict__ Yp, const float* __restrict__ Pp,
                      const float* __restrict__ b, const float* __restrict__ eta,
                      const float* __restrict__ g, const float* __restrict__ be,
                      const float* __restrict__ invn_in,
                      float* __restrict__ act, float* __restrict__ invn_out,
                      int H, int nsplit)
{
    __shared__ float sb[256];
    int r = blockIdx.x, o = threadIdx.x;
    size_t MN = (size_t)NB * H;
    size_t off = (size_t)r * H + o;
    float ys = b[o], pv = 0.f;
    for (int s = 0; s < nsplit; s++) { ys += Yp[s * MN + off]; pv += Pp[s * MN + off]; }
    float y = fmaf(eta[0] * tanhf(ys), invn_in[r] * pv, ys);
    float invH = 1.0f / (float)H;
    float s1 = blockReduce(y, sb, o, H);
    float s2 = blockReduce(y * y, sb, o, H);
    float mu = s1 * invH;
    float var = fmaf(s2, invH, -mu * mu);
    float ln = (y - mu) * rsqrtf(var + 1e-5f) * g[o] + be[o];
    float a = 0.5f * ln * (1.0f + erff(ln * 0.70710678118654752f));
    act[off] = a;
    float s3 = blockReduce(a * a, sb, o, H);
    if (o == 0) invn_out[r] = 1.0f / (sqrtf(s3) + 1e-8f);
}

// ------------- head -------------
__global__ void head_k(const float* __restrict__ act, const float* __restrict__ hw,
                       const float* __restrict__ hb, float* __restrict__ out)
{
    int t = threadIdx.x;
    int warp = t >> 5, lane = t & 31;
    int r = blockIdx.x * 32 + warp;
    const float* a = act + (size_t)r * 64;
    float v = fmaf(a[lane], hw[lane], a[lane + 32] * hw[lane + 32]);
    #pragma unroll
    for (int off = 16; off > 0; off >>= 1) v += __shfl_down_sync(0xffffffffu, v, off);
    if (lane == 0) out[r] = v + hb[0];
}

// ---------------- host launch ----------------
extern "C" void kernel_launch(void* const* d_in, const int* in_sizes, int n_in,
                              void* d_out, int out_size)
{
    (void)in_sizes; (void)n_in; (void)out_size;
    const float* x    = (const float*)d_in[0];
    const float* W0   = (const float*)d_in[1];
    const float* al0  = (const float*)d_in[2];
    const float* b0   = (const float*)d_in[3];
    const float* eta0 = (const float*)d_in[4];
    const float* g0   = (const float*)d_in[5];
    const float* be0  = (const float*)d_in[6];
    const float* W1   = (const float*)d_in[7];
    const float* al1  = (const float*)d_in[8];
    const float* b1   = (const float*)d_in[9];
    const float* eta1 = (const float*)d_in[10];
    const float* g1   = (const float*)d_in[11];
    const float* be1  = (const float*)d_in[12];
    const float* W2   = (const float*)d_in[13];
    const float* al2  = (const float*)d_in[14];
    const float* b2   = (const float*)d_in[15];
    const float* eta2 = (const float*)d_in[16];
    const float* g2   = (const float*)d_in[17];
    const float* be2  = (const float*)d_in[18];
    const float* hw   = (const float*)d_in[19];
    const float* hb   = (const float*)d_in[20];
    float* out = (float*)d_out;

    float *pS1, *pS2, *pYp, *pPp, *pa1, *pa2, *pa3, *pi0, *pi1, *pi2, *pi3;
    cudaGetSymbolAddress((void**)&pS1, g_S1);
    cudaGetSymbolAddress((void**)&pS2, g_S2);
    cudaGetSymbolAddress((void**)&pYp, g_Yp);
    cudaGetSymbolAddress((void**)&pPp, g_Pp);
    cudaGetSymbolAddress((void**)&pa1, g_act1);
    cudaGetSymbolAddress((void**)&pa2, g_act2);
    cudaGetSymbolAddress((void**)&pa3, g_act3);
    cudaGetSymbolAddress((void**)&pi0, g_invn0);
    cudaGetSymbolAddress((void**)&pi1, g_invn1);
    cudaGetSymbolAddress((void**)&pi2, g_invn2);
    cudaGetSymbolAddress((void**)&pi3, g_invn3);

    const int SMEM_FFT = (20000 + 2000) * (int)sizeof(float2);  // 176000 B
    cudaFuncSetAttribute(fft_k, cudaFuncAttributeMaxDynamicSharedMemorySize, SMEM_FFT);

    twiddle_init_k<<<8, 256>>>();
    sigmoid_k<<<64, 256>>>(al1, pS1, 128 * 256);
    sigmoid_k<<<16, 256>>>(al2, pS2, 64 * 128);
    convW_k<<<512, 256>>>(W0, al0);

    fft_k<<<NPAIR, 1024, SMEM_FFT>>>(x);

    tgemm0_k<<<dim3(4, 16, TSPLIT), 128>>>(pYp, pPp);
    epi_k<<<NB, 256>>>(pYp, pPp, b0, eta0, g0, be0, pi0, pa1, pi1, 256, TSPLIT);

    int Kc1 = ((256 + NSPLIT * 16 - 1) / (NSPLIT * 16)) * 16;  // 64
    int Kc2 = ((128 + NSPLIT * 16 - 1) / (NSPLIT * 16)) * 16;  // 32
    gemm_dual_k<<<dim3(128 / 64, NB / 64, NSPLIT), 256>>>(pa1, W1, pS1, pYp, pPp, NB, 128, 256, Kc1);
    epi_k<<<NB, 128>>>(pYp, pPp, b1, eta1, g1, be1, pi1, pa2, pi2, 128, NSPLIT);
    gemm_dual_k<<<dim3(64 / 64,  NB / 64, NSPLIT), 256>>>(pa2, W2, pS2, pYp, pPp, NB, 64, 128, Kc2);
    epi_k<<<NB, 64>>>(pYp, pPp, b2, eta2, g2, be2, pi2, pa3, pi3, 64, NSPLIT);
    head_k<<<NB / 32, 1024>>>(pa3, hw, hb, out);
}